// round 14
// baseline (speedup 1.0000x reference)
#include <cuda_runtime.h>
#include <cuda_fp16.h>
#include <cstdint>

#define BATCH 4
#define SEQ   2048
#define DIM   2048
#define M_TOT (BATCH*SEQ)     // 8192
#define NCH   128
#define CHLEN (SEQ/NCH)       // 16

#define BM 128
#define BN 128
#define BK 64
#define NSTAGE 3
#define NTHREADS 128          // 4 warps, 2x2 grid of 64x64 warp tiles

// ---------------- scratch (device globals; no allocation allowed) ----------------
__device__ __align__(16) __half g_Xq [M_TOT*DIM];        // quantized x (integer k as fp16)
__device__ __align__(16) __half g_Wi [DIM*DIM];          // w_i^T  [N][K]
__device__ __align__(16) __half g_Wf [DIM*DIM];
__device__ __align__(16) __half g_Wg [DIM*DIM];
__device__ __align__(16) __half g_Wo [DIM*DIM];          // w_o fp16 [N][K], single copy
__device__ __align__(16) float  g_Yi [M_TOT*DIM];        // raw i; later reused as Lo buffer
__device__ __align__(16) float  g_Yf [M_TOT*DIM];        // f = sigmoid(raw)
__device__ __align__(16) float  g_Yg [M_TOT*DIM];        // gsw = g*sigmoid(g)
__device__ __align__(16) __half g_A2 [M_TOT*2*DIM];      // (o*s_o) split hi|lo
__device__ float g_P [NCH*BATCH*DIM];
__device__ float g_Hc[NCH*BATCH*DIM];
__device__ float g_Cr[NCH*BATCH*DIM];

// ---------------- PTX helpers ----------------
__device__ __forceinline__ void cp16(uint32_t s, const void* g) {
    asm volatile("cp.async.cg.shared.global [%0], [%1], 16;\n" :: "r"(s), "l"(g));
}
__device__ __forceinline__ void cp_commit() { asm volatile("cp.async.commit_group;\n"); }
template<int N> __device__ __forceinline__ void cp_wait() {
    asm volatile("cp.async.wait_group %0;\n" :: "n"(N));
}
__device__ __forceinline__ void ldsm4(uint32_t& r0, uint32_t& r1, uint32_t& r2, uint32_t& r3, uint32_t a) {
    asm volatile("ldmatrix.sync.aligned.m8n8.x4.shared.b16 {%0,%1,%2,%3},[%4];\n"
                 : "=r"(r0), "=r"(r1), "=r"(r2), "=r"(r3) : "r"(a));
}
__device__ __forceinline__ void mma16816(float* c, const uint32_t* a, const uint32_t* b) {
    asm volatile("mma.sync.aligned.m16n8k16.row.col.f32.f16.f16.f32 "
                 "{%0,%1,%2,%3},{%4,%5,%6,%7},{%8,%9},{%0,%1,%2,%3};\n"
                 : "+f"(c[0]), "+f"(c[1]), "+f"(c[2]), "+f"(c[3])
                 : "r"(a[0]), "r"(a[1]), "r"(a[2]), "r"(a[3]), "r"(b[0]), "r"(b[1]));
}
// f16-accumulator HMMA (2x rate on legacy path if available)
__device__ __forceinline__ void mma16816h(uint32_t* c, const uint32_t* a, const uint32_t* b) {
    asm volatile("mma.sync.aligned.m16n8k16.row.col.f16.f16.f16.f16 "
                 "{%0,%1},{%2,%3,%4,%5},{%6,%7},{%0,%1};\n"
                 : "+r"(c[0]), "+r"(c[1])
                 : "r"(a[0]), "r"(a[1]), "r"(a[2]), "r"(a[3]), "r"(b[0]), "r"(b[1]));
}
// swizzled half-index inside a BMxBK stage (rows of 64 halfs = 8 chunks of 16B)
__device__ __forceinline__ uint32_t swz(int row, int k) {
    return (uint32_t)(row*BK + ((((k >> 3) ^ (row & 7)) << 3) | (k & 7)));
}
__device__ __forceinline__ float fsig(float x) {   // fast sigmoid via MUFU ex2 path
    return 1.f / (1.f + __expf(-x));
}

// ---------------- elementwise kernels ----------------
__global__ void k_quant(const float* __restrict__ hs) {
    int i = blockIdx.x * 256 + threadIdx.x;
    const float4 v = ((const float4*)hs)[i];
    __half h[4];
    h[0] = __float2half_rn(rintf(v.x * 256.f));
    h[1] = __float2half_rn(rintf(v.y * 256.f));
    h[2] = __float2half_rn(rintf(v.z * 256.f));
    h[3] = __float2half_rn(rintf(v.w * 256.f));
    ((uint2*)g_Xq)[i] = *(uint2*)h;
}

__global__ void k_transpose(const float* __restrict__ wi, const float* __restrict__ wf,
                            const float* __restrict__ wg) {
    __shared__ float tile[32][33];
    int z = blockIdx.z;
    const float* src = (z == 0) ? wi : (z == 1) ? wf : wg;
    __half* dst = (z == 0) ? g_Wi : (z == 1) ? g_Wf : g_Wg;
    int k0 = blockIdx.y * 32, n0 = blockIdx.x * 32;
    int tx = threadIdx.x, ty = threadIdx.y;     // 32 x 8
    #pragma unroll
    for (int j = 0; j < 32; j += 8)
        tile[ty + j][tx] = src[(size_t)(k0 + ty + j) * DIM + n0 + tx];
    __syncthreads();
    #pragma unroll
    for (int j = 0; j < 32; j += 8)
        dst[(size_t)(n0 + ty + j) * DIM + k0 + tx] = __float2half_rn(tile[tx][ty + j]);
}

__global__ void k_wo(const float* __restrict__ wo) {
    int i = blockIdx.x * 256 + threadIdx.x;       // float4 index over DIM*DIM/4
    const float4 v = ((const float4*)wo)[i];
    __half h[4];
    h[0] = __float2half_rn(v.x);                  // ternary: exact
    h[1] = __float2half_rn(v.y);
    h[2] = __float2half_rn(v.z);
    h[3] = __float2half_rn(v.w);
    ((uint2*)g_Wo)[i] = *(uint2*)h;
}

// ---------------- GEMM1: C[M,N] = A[M,K] * B[N,K]^T (fp16 in, fp32 acc) ----------------
// 4 warps, 64x64 warp tiles, 3-stage cp.async ring.  (R8 known-good schedule — DO NOT TOUCH)
__global__ void __launch_bounds__(NTHREADS, 2) k_gemm(
    const __half* __restrict__ A,
    const __half* __restrict__ B0, const __half* __restrict__ B1,
    const __half* __restrict__ B2,
    float* C0, float* C1, float* C2,
    const float* s0, const float* s1, const float* s2,
    int K, int mode)
{
    extern __shared__ __half sm[];
    constexpr int STAGE_H = BM * BK + BN * BK;    // halfs per stage
    int z = blockIdx.z;
    const __half* Bw = (z == 0) ? B0 : (z == 1) ? B1 : B2;
    float* Cc        = (z == 0) ? C0 : (z == 1) ? C1 : C2;
    const float* sp  = (z == 0) ? s0 : (z == 1) ? s1 : s2;

    int bm = blockIdx.y * BM, bn = blockIdx.x * BN;
    const __half* Ag = A  + (size_t)bm * K;
    const __half* Bg = Bw + (size_t)bn * K;
    int tid = threadIdx.x;
    uint32_t sbase = (uint32_t)__cvta_generic_to_shared(sm);
    int KT = K / BK;

    int lane = tid & 31, w = tid >> 5;
    int wm = (w >> 1) * 64, wn = (w & 1) * 64;   // 2x2 warp grid, warp tile 64x64
    int g = lane >> 2, t2 = (lane & 3) << 1;
    int r = lane & 7, sub = lane >> 3;

    float acc[4][8][4];
    #pragma unroll
    for (int a = 0; a < 4; a++)
        #pragma unroll
        for (int b = 0; b < 8; b++)
            #pragma unroll
            for (int c = 0; c < 4; c++) acc[a][b][c] = 0.f;

    // stage loader: 128 threads, 8 x 16B each for A and B
    auto load = [&](int st, int kt) {
        int kb = kt * BK;
        uint32_t sA = sbase + (uint32_t)(st * STAGE_H) * 2;
        uint32_t sB = sA + (uint32_t)(BM * BK) * 2;
        #pragma unroll
        for (int i = 0; i < 8; i++) {
            int v = tid + i * NTHREADS;
            int row = v >> 3, ch = v & 7;
            uint32_t so = (uint32_t)(swz(row, ch * 8) * 2);
            cp16(sA + so, Ag + (size_t)row * K + kb + ch * 8);
            cp16(sB + so, Bg + (size_t)row * K + kb + ch * 8);
        }
    };

    // prologue: fill NSTAGE-1 stages
    load(0, 0); cp_commit();
    load(1, 1); cp_commit();

    for (int kt = 0; kt < KT; kt++) {
        cp_wait<NSTAGE - 2>();       // stage kt resident
        __syncthreads();
        if (kt + NSTAGE - 1 < KT) load((kt + NSTAGE - 1) % NSTAGE, kt + NSTAGE - 1);
        cp_commit();                 // uniform group counting

        int stb = (kt % NSTAGE) * STAGE_H;
        uint32_t sA = sbase + (uint32_t)stb * 2;
        uint32_t sB = sA + (uint32_t)(BM * BK) * 2;
        #pragma unroll
        for (int ks = 0; ks < 4; ks++) {
            int ko = ks * 16;
            uint32_t a[4][4], b[8][2];
            #pragma unroll
            for (int mi = 0; mi < 4; mi++) {
                int row = wm + mi * 16 + r + ((sub & 1) << 3);
                int kk  = ko + ((sub >> 1) << 3);
                ldsm4(a[mi][0], a[mi][1], a[mi][2], a[mi][3],
                      sA + (uint32_t)(swz(row, kk) * 2));
            }
            #pragma unroll
            for (int p = 0; p < 4; p++) {
                int rown = wn + p * 16 + r + ((sub >> 1) << 3);
                int kk   = ko + ((sub & 1) << 3);
                ldsm4(b[2*p][0], b[2*p][1], b[2*p+1][0], b[2*p+1][1],
                      sB + (uint32_t)(swz(rown, kk) * 2));
            }
            #pragma unroll
            for (int mi = 0; mi < 4; mi++)
                #pragma unroll
                for (int ni = 0; ni < 8; ni++)
                    mma16816(acc[mi][ni], a[mi], b[ni]);
        }
    }

    const float inv256 = 1.f / 256.f;
    #pragma unroll
    for (int mi = 0; mi < 4; mi++) {
        #pragma unroll
        for (int ni = 0; ni < 8; ni++) {
            int row = bm + wm + mi * 16 + g;
            int col = bn + wn + ni * 8 + t2;
            float* c = acc[mi][ni];
            if (mode == 0) {
                float sa = sp[col] * inv256, sb = sp[col + 1] * inv256;
                float v0 = c[0] * sa, v1 = c[1] * sb, v2 = c[2] * sa, v3 = c[3] * sb;
                if (z == 1) {          // forget gate: store sigmoid
                    v0 = fsig(v0); v1 = fsig(v1); v2 = fsig(v2); v3 = fsig(v3);
                } else if (z == 2) {   // output gate: store swish
                    v0 = v0 * fsig(v0); v1 = v1 * fsig(v1);
                    v2 = v2 * fsig(v2); v3 = v3 * fsig(v3);
                }
                Cc[(size_t)row * DIM + col]           = v0;
                Cc[(size_t)row * DIM + col + 1]       = v1;
                Cc[(size_t)(row + 8) * DIM + col]     = v2;
                Cc[(size_t)(row + 8) * DIM + col + 1] = v3;
            } else {  // to_fixed(acc)
                Cc[(size_t)row * DIM + col]           = rintf(c[0] * 256.f) * inv256;
                Cc[(size_t)row * DIM + col + 1]       = rintf(c[1] * 256.f) * inv256;
                Cc[(size_t)(row + 8) * DIM + col]     = rintf(c[2] * 256.f) * inv256;
                Cc[(size_t)(row + 8) * DIM + col + 1] = rintf(c[3] * 256.f) * inv256;
            }
        }
    }
}

// ---------------- GEMM2-lo: Lo[M,N] = A_lo[M,2048] * Wo^T, f16 accumulators ----------------
// AS = A row stride. Dual f16 accumulators (kt parity) halve the rounding chain.
template<int AS>
__global__ void __launch_bounds__(NTHREADS, 2) k_gemm2lo(
    const __half* __restrict__ A, const __half* __restrict__ Bw, float* __restrict__ Lo)
{
    extern __shared__ __half sm[];
    constexpr int STAGE_H = BM * BK + BN * BK;
    constexpr int KT = DIM / BK;                 // 32

    int bm = blockIdx.y * BM, bn = blockIdx.x * BN;
    const __half* Ag = A  + (size_t)bm * AS;
    const __half* Bg = Bw + (size_t)bn * DIM;
    int tid = threadIdx.x;
    uint32_t sbase = (uint32_t)__cvta_generic_to_shared(sm);

    int lane = tid & 31, w = tid >> 5;
    int wm = (w >> 1) * 64, wn = (w & 1) * 64;
    int g = lane >> 2, t2 = (lane & 3) << 1;
    int r = lane & 7, sub = lane >> 3;

    uint32_t accE[4][8][2], accO[4][8][2];
    #pragma unroll
    for (int a = 0; a < 4; a++)
        #pragma unroll
        for (int b = 0; b < 8; b++) {
            accE[a][b][0] = accE[a][b][1] = 0u;
            accO[a][b][0] = accO[a][b][1] = 0u;
        }

    auto load = [&](int st, int kt) {
        int kb = kt * BK;
        uint32_t sA = sbase + (uint32_t)(st * STAGE_H) * 2;
        uint32_t sB = sA + (uint32_t)(BM * BK) * 2;
        #pragma unroll
        for (int i = 0; i < 8; i++) {
            int v = tid + i * NTHREADS;
            int row = v >> 3, ch = v & 7;
            uint32_t so = (uint32_t)(swz(row, ch * 8) * 2);
            cp16(sA + so, Ag + (size_t)row * AS + kb + ch * 8);
            cp16(sB + so, Bg + (size_t)row * DIM + kb + ch * 8);
        }
    };

    load(0, 0); cp_commit();
    load(1, 1); cp_commit();

    for (int kt = 0; kt < KT; kt++) {
        cp_wait<NSTAGE - 2>();
        __syncthreads();
        if (kt + NSTAGE - 1 < KT) load((kt + NSTAGE - 1) % NSTAGE, kt + NSTAGE - 1);
        cp_commit();

        int stb = (kt % NSTAGE) * STAGE_H;
        uint32_t sA = sbase + (uint32_t)stb * 2;
        uint32_t sB = sA + (uint32_t)(BM * BK) * 2;
        uint32_t (*acc)[8][2] = (kt & 1) ? accO : accE;
        #pragma unroll
        for (int ks = 0; ks < 4; ks++) {
            int ko = ks * 16;
            uint32_t a[4][4], b[8][2];
            #pragma unroll
            for (int mi = 0; mi < 4; mi++) {
                int row = wm + mi * 16 + r + ((sub & 1) << 3);
                int kk  = ko + ((sub >> 1) << 3);
                ldsm4(a[mi][0], a[mi][1], a[mi][2], a[mi][3],
                      sA + (uint32_t)(swz(row, kk) * 2));
            }
            #pragma unroll
            for (int p = 0; p < 4; p++) {
                int rown = wn + p * 16 + r + ((sub >> 1) << 3);
                int kk   = ko + ((sub & 1) << 3);
                ldsm4(b[2*p][0], b[2*p][1], b[2*p+1][0], b[2*p+1][1],
                      sB + (uint32_t)(swz(rown, kk) * 2));
            }
            #pragma unroll
            for (int mi = 0; mi < 4; mi++)
                #pragma unroll
                for (int ni = 0; ni < 8; ni++)
                    mma16816h(acc[mi][ni], a[mi], b[ni]);
        }
    }

    #pragma unroll
    for (int mi = 0; mi < 4; mi++) {
        #pragma unroll
        for (int ni = 0; ni < 8; ni++) {
            int row = bm + wm + mi * 16 + g;
            int col = bn + wn + ni * 8 + t2;
            __half2 e0 = *(__half2*)&accE[mi][ni][0];
            __half2 e1 = *(__half2*)&accE[mi][ni][1];
            __half2 o0 = *(__half2*)&accO[mi][ni][0];
            __half2 o1 = *(__half2*)&accO[mi][ni][1];
            Lo[(size_t)row * DIM + col]           = __low2float(e0)  + __low2float(o0);
            Lo[(size_t)row * DIM + col + 1]       = __high2float(e0) + __high2float(o0);
            Lo[(size_t)(row + 8) * DIM + col]     = __low2float(e1)  + __low2float(o1);
            Lo[(size_t)(row + 8) * DIM + col + 1] = __high2float(e1) + __high2float(o1);
        }
    }
}

// ---------------- GEMM2-hi: out = to_fixed(A_hi * Wo^T + Lo), f32 acc, K=2048 ----------------
template<int AS>
__global__ void __launch_bounds__(NTHREADS, 2) k_gemm2hi(
    const __half* __restrict__ A, const __half* __restrict__ Bw,
    const float* __restrict__ Lo, float* __restrict__ Cc)
{
    extern __shared__ __half sm[];
    constexpr int STAGE_H = BM * BK + BN * BK;
    constexpr int KT = DIM / BK;

    int bm = blockIdx.y * BM, bn = blockIdx.x * BN;
    const __half* Ag = A  + (size_t)bm * AS;
    const __half* Bg = Bw + (size_t)bn * DIM;
    int tid = threadIdx.x;
    uint32_t sbase = (uint32_t)__cvta_generic_to_shared(sm);

    int lane = tid & 31, w = tid >> 5;
    int wm = (w >> 1) * 64, wn = (w & 1) * 64;
    int g = lane >> 2, t2 = (lane & 3) << 1;
    int r = lane & 7, sub = lane >> 3;

    float acc[4][8][4];
    #pragma unroll
    for (int a = 0; a < 4; a++)
        #pragma unroll
        for (int b = 0; b < 8; b++)
            #pragma unroll
            for (int c = 0; c < 4; c++) acc[a][b][c] = 0.f;

    auto load = [&](int st, int kt) {
        int kb = kt * BK;
        uint32_t sA = sbase + (uint32_t)(st * STAGE_H) * 2;
        uint32_t sB = sA + (uint32_t)(BM * BK) * 2;
        #pragma unroll
        for (int i = 0; i < 8; i++) {
            int v = tid + i * NTHREADS;
            int row = v >> 3, ch = v & 7;
            uint32_t so = (uint32_t)(swz(row, ch * 8) * 2);
            cp16(sA + so, Ag + (size_t)row * AS + kb + ch * 8);
            cp16(sB + so, Bg + (size_t)row * DIM + kb + ch * 8);
        }
    };

    load(0, 0); cp_commit();
    load(1, 1); cp_commit();

    for (int kt = 0; kt < KT; kt++) {
        cp_wait<NSTAGE - 2>();
        __syncthreads();
        if (kt + NSTAGE - 1 < KT) load((kt + NSTAGE - 1) % NSTAGE, kt + NSTAGE - 1);
        cp_commit();

        int stb = (kt % NSTAGE) * STAGE_H;
        uint32_t sA = sbase + (uint32_t)stb * 2;
        uint32_t sB = sA + (uint32_t)(BM * BK) * 2;
        #pragma unroll
        for (int ks = 0; ks < 4; ks++) {
            int ko = ks * 16;
            uint32_t a[4][4], b[8][2];
            #pragma unroll
            for (int mi = 0; mi < 4; mi++) {
                int row = wm + mi * 16 + r + ((sub & 1) << 3);
                int kk  = ko + ((sub >> 1) << 3);
                ldsm4(a[mi][0], a[mi][1], a[mi][2], a[mi][3],
                      sA + (uint32_t)(swz(row, kk) * 2));
            }
            #pragma unroll
            for (int p = 0; p < 4; p++) {
                int rown = wn + p * 16 + r + ((sub >> 1) << 3);
                int kk   = ko + ((sub & 1) << 3);
                ldsm4(b[2*p][0], b[2*p][1], b[2*p+1][0], b[2*p+1][1],
                      sB + (uint32_t)(swz(rown, kk) * 2));
            }
            #pragma unroll
            for (int mi = 0; mi < 4; mi++)
                #pragma unroll
                for (int ni = 0; ni < 8; ni++)
                    mma16816(acc[mi][ni], a[mi], b[ni]);
        }
    }

    const float inv256 = 1.f / 256.f;
    #pragma unroll
    for (int mi = 0; mi < 4; mi++) {
        #pragma unroll
        for (int ni = 0; ni < 8; ni++) {
            int row = bm + wm + mi * 16 + g;
            int col = bn + wn + ni * 8 + t2;
            float* c = acc[mi][ni];
            float l0 = Lo[(size_t)row * DIM + col];
            float l1 = Lo[(size_t)row * DIM + col + 1];
            float l2 = Lo[(size_t)(row + 8) * DIM + col];
            float l3 = Lo[(size_t)(row + 8) * DIM + col + 1];
            Cc[(size_t)row * DIM + col]           = rintf((c[0] + l0) * 256.f) * inv256;
            Cc[(size_t)row * DIM + col + 1]       = rintf((c[1] + l1) * 256.f) * inv256;
            Cc[(size_t)(row + 8) * DIM + col]     = rintf((c[2] + l2) * 256.f) * inv256;
            Cc[(size_t)(row + 8) * DIM + col + 1] = rintf((c[3] + l3) * 256.f) * inv256;
        }
    }
}

// ---------------- chunked linear-recurrence scan (f precomputed) ----------------
__global__ void k_scan1() {
    int d4 = blockIdx.x * 128 + threadIdx.x;        // float4 index within DIM/4
    int c = blockIdx.y, b = blockIdx.z;
    size_t base = ((size_t)(b * SEQ + c * CHLEN)) * (DIM/4) + d4;
    const float4* Yf4 = (const float4*)g_Yf;
    const float4* Yi4 = (const float4*)g_Yi;
    float4 P = make_float4(1.f,1.f,1.f,1.f), H = make_float4(0.f,0.f,0.f,0.f);
    #pragma unroll
    for (int t = 0; t < CHLEN; t++) {
        float4 f  = Yf4[base + (size_t)t * (DIM/4)];
        float4 yi = Yi4[base + (size_t)t * (DIM/4)];
        P.x *= f.x; P.y *= f.y; P.z *= f.z; P.w *= f.w;
        H.x = fmaf(f.x, H.x, (1.f - f.x) * yi.x);
        H.y = fmaf(f.y, H.y, (1.f - f.y) * yi.y);
        H.z = fmaf(f.z, H.z, (1.f - f.z) * yi.z);
        H.w = fmaf(f.w, H.w, (1.f - f.w) * yi.w);
    }
    int o = (c * BATCH + b) * (DIM/4) + d4;
    ((float4*)g_P)[o] = P; ((float4*)g_Hc)[o] = H;
}

__global__ void k_scan2() {
    int idx = blockIdx.x * 256 + threadIdx.x;   // 0..B*DIM/4-1
    float4 h = make_float4(0.f,0.f,0.f,0.f);
    #pragma unroll 8
    for (int c = 0; c < NCH; c++) {
        int o = c * (BATCH * DIM / 4) + idx;
        ((float4*)g_Cr)[o] = h;
        float4 P = ((const float4*)g_P)[o];
        float4 Hc = ((const float4*)g_Hc)[o];
        h.x = fmaf(P.x, h.x, Hc.x); h.y = fmaf(P.y, h.y, Hc.y);
        h.z = fmaf(P.z, h.z, Hc.z); h.w = fmaf(P.w, h.w, Hc.w);
    }
}

// ---------------- fused finalize-scan + RMSNorm + gate + hi/lo split ----------------
__global__ void __launch_bounds__(512, 2) k_scan3norm(
    const float* __restrict__ so, const float* __restrict__ gnw)
{
    int c = blockIdx.x, b = blockIdx.y;
    int d4 = threadIdx.x;                         // 0..511, covers dims 4*d4..4*d4+3
    int lane = d4 & 31, wid = d4 >> 5;
    size_t base = ((size_t)(b * SEQ + c * CHLEN)) * (DIM/4) + d4;
    const float4* Yf4 = (const float4*)g_Yf;
    const float4* Yi4 = (const float4*)g_Yi;
    const float4* Yg4 = (const float4*)g_Yg;

    float4 sv = ((const float4*)so)[d4];
    float4 wv = ((const float4*)gnw)[d4];
    float4 cs = make_float4(wv.x * sv.x, wv.y * sv.y, wv.z * sv.z, wv.w * sv.w);

    float4 h = ((const float4*)g_Cr)[(c * BATCH + b) * (DIM/4) + d4];

    __shared__ float red[16];
    __shared__ float tot;

    for (int t = 0; t < CHLEN; t++) {
        size_t off = base + (size_t)t * (DIM/4);
        float4 f  = Yf4[off];
        float4 yi = Yi4[off];
        h.x = fmaf(f.x, h.x, (1.f - f.x) * yi.x);
        h.y = fmaf(f.y, h.y, (1.f - f.y) * yi.y);
        h.z = fmaf(f.z, h.z, (1.f - f.z) * yi.z);
        h.w = fmaf(f.w, h.w, (1.f - f.w) * yi.w);

        float ss = h.x*h.x + h.y*h.y + h.z*h.z + h.w*h.w;
        #pragma unroll
        for (int o = 16; o; o >>= 1) ss += __shfl_xor_sync(0xffffffffu, ss, o);
        if (lane == 0) red[wid] = ss;
        __syncthreads();
        if (wid == 0) {
            float v = (lane < 16) ? red[lane] : 0.f;
            #pragma unroll
            for (int o = 8; o; o >>= 1) v += __shfl_xor_sync(0xffffffffu, v, o);
            if (lane == 0) tot = v;
        }
        __syncthreads();
        float rms = rsqrtf(tot * (1.f / DIM) + 1e-5f);

        float4 gv = Yg4[off];          // already g*sigmoid(g)
        float q[4];
        q[0] = h.x * rms * cs.x * gv.x;
        q[1] = h.y * rms * cs.y * gv.y;
        q[2] = h.z * rms * cs.z * gv.z;
        q[3] = h.w * rms * cs.w * gv.w;
        __half hi[4]; __half lo[4];
        #pragma unroll
        for (int u = 0; u < 4; u++) {
            hi[u] = __float2half_rn(q[u]);
            lo[u] = __float2half_rn(q[u] - __half2float(hi[u]));
        }
        size_t m = (size_t)(b * SEQ + c * CHLEN + t);
        ((uint2*)(g_A2 + m * (2*DIM)))[d4]       = *(uint2*)hi;
        ((uint2*)(g_A2 + m * (2*DIM) + DIM))[d4] = *(uint2*)lo;
    }
}

// ---------------- launch ----------------
extern "C" void kernel_launch(void* const* d_in, const int* in_sizes, int n_in,
                              void* d_out, int out_size) {
    const float* hs  = (const float*)d_in[0];
    const float* wi  = (const float*)d_in[1];
    const float* wf  = (const float*)d_in[2];
    const float* wg  = (const float*)d_in[3];
    const float* wo  = (const float*)d_in[4];
    const float* si  = (const float*)d_in[5];
    const float* sf  = (const float*)d_in[6];
    const float* sg  = (const float*)d_in[7];
    const float* so  = (const float*)d_in[8];
    const float* gnw = (const float*)d_in[9];

    __half *Xq, *Wi, *Wf, *Wg, *Wo, *A2;
    float  *Yi, *Yf, *Yg;
    cudaGetSymbolAddress((void**)&Xq,  g_Xq);
    cudaGetSymbolAddress((void**)&Wi,  g_Wi);
    cudaGetSymbolAddress((void**)&Wf,  g_Wf);
    cudaGetSymbolAddress((void**)&Wg,  g_Wg);
    cudaGetSymbolAddress((void**)&Wo,  g_Wo);
    cudaGetSymbolAddress((void**)&A2,  g_A2);
    cudaGetSymbolAddress((void**)&Yi,  g_Yi);
    cudaGetSymbolAddress((void**)&Yf,  g_Yf);
    cudaGetSymbolAddress((void**)&Yg,  g_Yg);

    const int smem = NSTAGE * (BM * BK + BN * BK) * 2;  // 96 KB
    cudaFuncSetAttribute(k_gemm, cudaFuncAttributeMaxDynamicSharedMemorySize, smem);
    cudaFuncSetAttribute((const void*)&k_gemm2lo<2*DIM>,
                         cudaFuncAttributeMaxDynamicSharedMemorySize, smem);
    cudaFuncSetAttribute((const void*)&k_gemm2hi<2*DIM>,
                         cudaFuncAttributeMaxDynamicSharedMemorySize, smem);

    k_quant<<<(M_TOT * DIM) / 1024, 256>>>(hs);
    k_transpose<<<dim3(DIM / 32, DIM / 32, 3), dim3(32, 8)>>>(wi, wf, wg);
    k_wo<<<(DIM * DIM) / 1024, 256>>>(wo);

    // i/f/g projections: exact integer fp16 MMA; epilogue applies scale + sigmoid/swish
    k_gemm<<<dim3(DIM / BN, M_TOT / BM, 3), NTHREADS, smem>>>(
        Xq, Wi, Wf, Wg, Yi, Yf, Yg, si, sf, sg, DIM, 0);

    k_scan1<<<dim3(DIM / 512, NCH, BATCH), 128>>>();
    k_scan2<<<(BATCH * DIM / 4) / 256, 256>>>();
    k_scan3norm<<<dim3(NCH, BATCH), 512>>>(so, gnw);

    // output projection split:
    //  lo-pass: f16-acc GEMM on the lo halves (writes Lo correction into retired Yi buffer)
    //  hi-pass: f32-acc GEMM on hi halves, epilogue adds Lo then to_fixed
    k_gemm2lo<2*DIM><<<dim3(DIM / BN, M_TOT / BM), NTHREADS, smem>>>(A2 + DIM, Wo, Yi);
    k_gemm2hi<2*DIM><<<dim3(DIM / BN, M_TOT / BM), NTHREADS, smem>>>(A2, Wo, Yi, (float*)d_out);
}

// round 15
// speedup vs baseline: 1.0805x; 1.0805x over previous
#include <cuda_runtime.h>
#include <cuda_fp16.h>
#include <cstdint>

#define BATCH 4
#define SEQ   2048
#define DIM   2048
#define M_TOT (BATCH*SEQ)     // 8192
#define NCH   128
#define CHLEN (SEQ/NCH)       // 16

#define BM 128
#define BN 128
#define BK 64
#define NSTAGE 3
#define NTHREADS 128          // 4 warps, 2x2 grid of 64x64 warp tiles

// ---------------- scratch (device globals; no allocation allowed) ----------------
__device__ __align__(16) __half g_Xq [M_TOT*DIM];        // quantized x (integer k as fp16)
__device__ __align__(16) __half g_Wi [DIM*DIM];          // w_i^T  [N][K]
__device__ __align__(16) __half g_Wf [DIM*DIM];
__device__ __align__(16) __half g_Wg [DIM*DIM];
__device__ __align__(16) __half g_Wo [DIM*DIM];          // w_o fp16 [N][K], single copy
__device__ __align__(16) float  g_Yi [M_TOT*DIM];        // raw i
__device__ __align__(16) float  g_Yf [M_TOT*DIM];        // f = sigmoid(raw)
__device__ __align__(16) float  g_Yg [M_TOT*DIM];        // gsw = g*sigmoid(g)
__device__ __align__(16) __half g_A2 [M_TOT*2*DIM];      // (o*s_o) split hi|lo
__device__ float g_P [NCH*BATCH*DIM];
__device__ float g_Hc[NCH*BATCH*DIM];
__device__ float g_Cr[NCH*BATCH*DIM];

// ---------------- PTX helpers ----------------
__device__ __forceinline__ void cp16(uint32_t s, const void* g) {
    asm volatile("cp.async.cg.shared.global [%0], [%1], 16;\n" :: "r"(s), "l"(g));
}
__device__ __forceinline__ void cp_commit() { asm volatile("cp.async.commit_group;\n"); }
template<int N> __device__ __forceinline__ void cp_wait() {
    asm volatile("cp.async.wait_group %0;\n" :: "n"(N));
}
__device__ __forceinline__ void ldsm4(uint32_t& r0, uint32_t& r1, uint32_t& r2, uint32_t& r3, uint32_t a) {
    asm volatile("ldmatrix.sync.aligned.m8n8.x4.shared.b16 {%0,%1,%2,%3},[%4];\n"
                 : "=r"(r0), "=r"(r1), "=r"(r2), "=r"(r3) : "r"(a));
}
__device__ __forceinline__ void mma16816(float* c, const uint32_t* a, const uint32_t* b) {
    asm volatile("mma.sync.aligned.m16n8k16.row.col.f32.f16.f16.f32 "
                 "{%0,%1,%2,%3},{%4,%5,%6,%7},{%8,%9},{%0,%1,%2,%3};\n"
                 : "+f"(c[0]), "+f"(c[1]), "+f"(c[2]), "+f"(c[3])
                 : "r"(a[0]), "r"(a[1]), "r"(a[2]), "r"(a[3]), "r"(b[0]), "r"(b[1]));
}
// swizzled half-index inside a BMxBK stage (rows of 64 halfs = 8 chunks of 16B)
__device__ __forceinline__ uint32_t swz(int row, int k) {
    return (uint32_t)(row*BK + ((((k >> 3) ^ (row & 7)) << 3) | (k & 7)));
}
__device__ __forceinline__ float fsig(float x) {   // fast sigmoid via MUFU ex2 path
    return 1.f / (1.f + __expf(-x));
}

// ---------------- elementwise kernels ----------------
__global__ void k_quant(const float* __restrict__ hs) {
    int i = blockIdx.x * 256 + threadIdx.x;
    const float4 v = ((const float4*)hs)[i];
    __half h[4];
    h[0] = __float2half_rn(rintf(v.x * 256.f));
    h[1] = __float2half_rn(rintf(v.y * 256.f));
    h[2] = __float2half_rn(rintf(v.z * 256.f));
    h[3] = __float2half_rn(rintf(v.w * 256.f));
    ((uint2*)g_Xq)[i] = *(uint2*)h;
}

// z<3: transpose+convert w_i/w_f/w_g to [N][K] fp16.  z==3: flat convert w_o.
__global__ void k_prepw(const float* __restrict__ wi, const float* __restrict__ wf,
                        const float* __restrict__ wg, const float* __restrict__ wo) {
    __shared__ float tile[32][33];
    int z = blockIdx.z;
    int tx = threadIdx.x, ty = threadIdx.y;     // 32 x 8
    if (z == 3) {
        int i = (blockIdx.y * 64 + blockIdx.x) * 256 + ty * 32 + tx;   // float4 idx
        const float4 v = ((const float4*)wo)[i];
        __half h[4];
        h[0] = __float2half_rn(v.x);            // ternary: exact
        h[1] = __float2half_rn(v.y);
        h[2] = __float2half_rn(v.z);
        h[3] = __float2half_rn(v.w);
        ((uint2*)g_Wo)[i] = *(uint2*)h;
        return;
    }
    const float* src = (z == 0) ? wi : (z == 1) ? wf : wg;
    __half* dst = (z == 0) ? g_Wi : (z == 1) ? g_Wf : g_Wg;
    int k0 = blockIdx.y * 32, n0 = blockIdx.x * 32;
    #pragma unroll
    for (int j = 0; j < 32; j += 8)
        tile[ty + j][tx] = src[(size_t)(k0 + ty + j) * DIM + n0 + tx];
    __syncthreads();
    #pragma unroll
    for (int j = 0; j < 32; j += 8)
        dst[(size_t)(n0 + ty + j) * DIM + k0 + tx] = __float2half_rn(tile[tx][ty + j]);
}

// ---------------- GEMM1: C[M,N] = A[M,K] * B[N,K]^T (fp16 in, fp32 acc) ----------------
// 4 warps, 64x64 warp tiles, 3-stage cp.async ring.  (R8 known-good schedule — DO NOT TOUCH)
__global__ void __launch_bounds__(NTHREADS, 2) k_gemm(
    const __half* __restrict__ A,
    const __half* __restrict__ B0, const __half* __restrict__ B1,
    const __half* __restrict__ B2,
    float* C0, float* C1, float* C2,
    const float* s0, const float* s1, const float* s2,
    int K, int mode)
{
    extern __shared__ __half sm[];
    constexpr int STAGE_H = BM * BK + BN * BK;    // halfs per stage
    int z = blockIdx.z;
    const __half* Bw = (z == 0) ? B0 : (z == 1) ? B1 : B2;
    float* Cc        = (z == 0) ? C0 : (z == 1) ? C1 : C2;
    const float* sp  = (z == 0) ? s0 : (z == 1) ? s1 : s2;

    int bm = blockIdx.y * BM, bn = blockIdx.x * BN;
    const __half* Ag = A  + (size_t)bm * K;
    const __half* Bg = Bw + (size_t)bn * K;
    int tid = threadIdx.x;
    uint32_t sbase = (uint32_t)__cvta_generic_to_shared(sm);
    int KT = K / BK;

    int lane = tid & 31, w = tid >> 5;
    int wm = (w >> 1) * 64, wn = (w & 1) * 64;   // 2x2 warp grid, warp tile 64x64
    int g = lane >> 2, t2 = (lane & 3) << 1;
    int r = lane & 7, sub = lane >> 3;

    float acc[4][8][4];
    #pragma unroll
    for (int a = 0; a < 4; a++)
        #pragma unroll
        for (int b = 0; b < 8; b++)
            #pragma unroll
            for (int c = 0; c < 4; c++) acc[a][b][c] = 0.f;

    // stage loader: 128 threads, 8 x 16B each for A and B
    auto load = [&](int st, int kt) {
        int kb = kt * BK;
        uint32_t sA = sbase + (uint32_t)(st * STAGE_H) * 2;
        uint32_t sB = sA + (uint32_t)(BM * BK) * 2;
        #pragma unroll
        for (int i = 0; i < 8; i++) {
            int v = tid + i * NTHREADS;
            int row = v >> 3, ch = v & 7;
            uint32_t so = (uint32_t)(swz(row, ch * 8) * 2);
            cp16(sA + so, Ag + (size_t)row * K + kb + ch * 8);
            cp16(sB + so, Bg + (size_t)row * K + kb + ch * 8);
        }
    };

    // prologue: fill NSTAGE-1 stages
    load(0, 0); cp_commit();
    load(1, 1); cp_commit();

    for (int kt = 0; kt < KT; kt++) {
        cp_wait<NSTAGE - 2>();       // stage kt resident
        __syncthreads();
        if (kt + NSTAGE - 1 < KT) load((kt + NSTAGE - 1) % NSTAGE, kt + NSTAGE - 1);
        cp_commit();                 // uniform group counting

        int stb = (kt % NSTAGE) * STAGE_H;
        uint32_t sA = sbase + (uint32_t)stb * 2;
        uint32_t sB = sA + (uint32_t)(BM * BK) * 2;
        #pragma unroll
        for (int ks = 0; ks < 4; ks++) {
            int ko = ks * 16;
            uint32_t a[4][4], b[8][2];
            #pragma unroll
            for (int mi = 0; mi < 4; mi++) {
                int row = wm + mi * 16 + r + ((sub & 1) << 3);
                int kk  = ko + ((sub >> 1) << 3);
                ldsm4(a[mi][0], a[mi][1], a[mi][2], a[mi][3],
                      sA + (uint32_t)(swz(row, kk) * 2));
            }
            #pragma unroll
            for (int p = 0; p < 4; p++) {
                int rown = wn + p * 16 + r + ((sub >> 1) << 3);
                int kk   = ko + ((sub & 1) << 3);
                ldsm4(b[2*p][0], b[2*p][1], b[2*p+1][0], b[2*p+1][1],
                      sB + (uint32_t)(swz(rown, kk) * 2));
            }
            #pragma unroll
            for (int mi = 0; mi < 4; mi++)
                #pragma unroll
                for (int ni = 0; ni < 8; ni++)
                    mma16816(acc[mi][ni], a[mi], b[ni]);
        }
    }

    const float inv256 = 1.f / 256.f;
    #pragma unroll
    for (int mi = 0; mi < 4; mi++) {
        #pragma unroll
        for (int ni = 0; ni < 8; ni++) {
            int row = bm + wm + mi * 16 + g;
            int col = bn + wn + ni * 8 + t2;
            float* c = acc[mi][ni];
            if (mode == 0) {
                float sa = sp[col] * inv256, sb = sp[col + 1] * inv256;
                float v0 = c[0] * sa, v1 = c[1] * sb, v2 = c[2] * sa, v3 = c[3] * sb;
                if (z == 1) {          // forget gate: store sigmoid
                    v0 = fsig(v0); v1 = fsig(v1); v2 = fsig(v2); v3 = fsig(v3);
                } else if (z == 2) {   // output gate: store swish
                    v0 = v0 * fsig(v0); v1 = v1 * fsig(v1);
                    v2 = v2 * fsig(v2); v3 = v3 * fsig(v3);
                }
                Cc[(size_t)row * DIM + col]           = v0;
                Cc[(size_t)row * DIM + col + 1]       = v1;
                Cc[(size_t)(row + 8) * DIM + col]     = v2;
                Cc[(size_t)(row + 8) * DIM + col + 1] = v3;
            } else {  // to_fixed(acc)
                Cc[(size_t)row * DIM + col]           = rintf(c[0] * 256.f) * inv256;
                Cc[(size_t)row * DIM + col + 1]       = rintf(c[1] * 256.f) * inv256;
                Cc[(size_t)(row + 8) * DIM + col]     = rintf(c[2] * 256.f) * inv256;
                Cc[(size_t)(row + 8) * DIM + col + 1] = rintf(c[3] * 256.f) * inv256;
            }
        }
    }
}

// ---------------- GEMM2: out = to_fixed(A[M,4096] * Wo[N,2048]^T dup over K) ----------------
// Templated (compile-time K/KB) single-B variant; B k-index = k & (KB-1).
template<int K, int KB>
__global__ void __launch_bounds__(NTHREADS, 2) k_gemm2(
    const __half* __restrict__ A, const __half* __restrict__ Bw, float* __restrict__ Cc)
{
    extern __shared__ __half sm[];
    constexpr int STAGE_H = BM * BK + BN * BK;
    constexpr int KT = K / BK;

    int bm = blockIdx.y * BM, bn = blockIdx.x * BN;
    const __half* Ag = A  + (size_t)bm * K;
    const __half* Bg = Bw + (size_t)bn * KB;
    int tid = threadIdx.x;
    uint32_t sbase = (uint32_t)__cvta_generic_to_shared(sm);

    int lane = tid & 31, w = tid >> 5;
    int wm = (w >> 1) * 64, wn = (w & 1) * 64;
    int g = lane >> 2, t2 = (lane & 3) << 1;
    int r = lane & 7, sub = lane >> 3;

    float acc[4][8][4];
    #pragma unroll
    for (int a = 0; a < 4; a++)
        #pragma unroll
        for (int b = 0; b < 8; b++)
            #pragma unroll
            for (int c = 0; c < 4; c++) acc[a][b][c] = 0.f;

    auto load = [&](int st, int kt) {
        int kb = kt * BK;
        int kbb = kb & (KB - 1);
        uint32_t sA = sbase + (uint32_t)(st * STAGE_H) * 2;
        uint32_t sB = sA + (uint32_t)(BM * BK) * 2;
        #pragma unroll
        for (int i = 0; i < 8; i++) {
            int v = tid + i * NTHREADS;
            int row = v >> 3, ch = v & 7;
            uint32_t so = (uint32_t)(swz(row, ch * 8) * 2);
            cp16(sA + so, Ag + (size_t)row * K + kb + ch * 8);
            cp16(sB + so, Bg + (size_t)row * KB + kbb + ch * 8);
        }
    };

    load(0, 0); cp_commit();
    load(1, 1); cp_commit();

    for (int kt = 0; kt < KT; kt++) {
        cp_wait<NSTAGE - 2>();
        __syncthreads();
        if (kt + NSTAGE - 1 < KT) load((kt + NSTAGE - 1) % NSTAGE, kt + NSTAGE - 1);
        cp_commit();

        int stb = (kt % NSTAGE) * STAGE_H;
        uint32_t sA = sbase + (uint32_t)stb * 2;
        uint32_t sB = sA + (uint32_t)(BM * BK) * 2;
        #pragma unroll
        for (int ks = 0; ks < 4; ks++) {
            int ko = ks * 16;
            uint32_t a[4][4], b[8][2];
            #pragma unroll
            for (int mi = 0; mi < 4; mi++) {
                int row = wm + mi * 16 + r + ((sub & 1) << 3);
                int kk  = ko + ((sub >> 1) << 3);
                ldsm4(a[mi][0], a[mi][1], a[mi][2], a[mi][3],
                      sA + (uint32_t)(swz(row, kk) * 2));
            }
            #pragma unroll
            for (int p = 0; p < 4; p++) {
                int rown = wn + p * 16 + r + ((sub >> 1) << 3);
                int kk   = ko + ((sub & 1) << 3);
                ldsm4(b[2*p][0], b[2*p][1], b[2*p+1][0], b[2*p+1][1],
                      sB + (uint32_t)(swz(rown, kk) * 2));
            }
            #pragma unroll
            for (int mi = 0; mi < 4; mi++)
                #pragma unroll
                for (int ni = 0; ni < 8; ni++)
                    mma16816(acc[mi][ni], a[mi], b[ni]);
        }
    }

    const float inv256 = 1.f / 256.f;
    #pragma unroll
    for (int mi = 0; mi < 4; mi++) {
        #pragma unroll
        for (int ni = 0; ni < 8; ni++) {
            int row = bm + wm + mi * 16 + g;
            int col = bn + wn + ni * 8 + t2;
            float* c = acc[mi][ni];
            Cc[(size_t)row * DIM + col]           = rintf(c[0] * 256.f) * inv256;
            Cc[(size_t)row * DIM + col + 1]       = rintf(c[1] * 256.f) * inv256;
            Cc[(size_t)(row + 8) * DIM + col]     = rintf(c[2] * 256.f) * inv256;
            Cc[(size_t)(row + 8) * DIM + col + 1] = rintf(c[3] * 256.f) * inv256;
        }
    }
}

// ---------------- chunked linear-recurrence scan (f precomputed) ----------------
__global__ void k_scan1() {
    int d4 = blockIdx.x * 128 + threadIdx.x;        // float4 index within DIM/4
    int c = blockIdx.y, b = blockIdx.z;
    size_t base = ((size_t)(b * SEQ + c * CHLEN)) * (DIM/4) + d4;
    const float4* Yf4 = (const float4*)g_Yf;
    const float4* Yi4 = (const float4*)g_Yi;
    float4 P = make_float4(1.f,1.f,1.f,1.f), H = make_float4(0.f,0.f,0.f,0.f);
    #pragma unroll
    for (int t = 0; t < CHLEN; t++) {
        float4 f  = Yf4[base + (size_t)t * (DIM/4)];
        float4 yi = Yi4[base + (size_t)t * (DIM/4)];
        P.x *= f.x; P.y *= f.y; P.z *= f.z; P.w *= f.w;
        H.x = fmaf(f.x, H.x, (1.f - f.x) * yi.x);
        H.y = fmaf(f.y, H.y, (1.f - f.y) * yi.y);
        H.z = fmaf(f.z, H.z, (1.f - f.z) * yi.z);
        H.w = fmaf(f.w, H.w, (1.f - f.w) * yi.w);
    }
    int o = (c * BATCH + b) * (DIM/4) + d4;
    ((float4*)g_P)[o] = P; ((float4*)g_Hc)[o] = H;
}

__global__ void k_scan2() {
    int idx = blockIdx.x * 256 + threadIdx.x;   // 0..B*DIM/4-1
    float4 h = make_float4(0.f,0.f,0.f,0.f);
    #pragma unroll 8
    for (int c = 0; c < NCH; c++) {
        int o = c * (BATCH * DIM / 4) + idx;
        ((float4*)g_Cr)[o] = h;
        float4 P = ((const float4*)g_P)[o];
        float4 Hc = ((const float4*)g_Hc)[o];
        h.x = fmaf(P.x, h.x, Hc.x); h.y = fmaf(P.y, h.y, Hc.y);
        h.z = fmaf(P.z, h.z, Hc.z); h.w = fmaf(P.w, h.w, Hc.w);
    }
}

// ---------------- fused finalize-scan + RMSNorm + gate + hi/lo split ----------------
// One CTA per (chunk, batch): 512 threads cover full DIM (4 dims/thread).
// Single __syncthreads per t-step via parity-double-buffered partials.
__global__ void __launch_bounds__(512, 2) k_scan3norm(
    const float* __restrict__ so, const float* __restrict__ gnw)
{
    int c = blockIdx.x, b = blockIdx.y;
    int d4 = threadIdx.x;                         // 0..511, covers dims 4*d4..4*d4+3
    int lane = d4 & 31, wid = d4 >> 5;
    size_t base = ((size_t)(b * SEQ + c * CHLEN)) * (DIM/4) + d4;
    const float4* Yf4 = (const float4*)g_Yf;
    const float4* Yi4 = (const float4*)g_Yi;
    const float4* Yg4 = (const float4*)g_Yg;

    float4 sv = ((const float4*)so)[d4];
    float4 wv = ((const float4*)gnw)[d4];
    float4 cs = make_float4(wv.x * sv.x, wv.y * sv.y, wv.z * sv.z, wv.w * sv.w);

    float4 h = ((const float4*)g_Cr)[(c * BATCH + b) * (DIM/4) + d4];

    __shared__ float red[2][16];

    for (int t = 0; t < CHLEN; t++) {
        size_t off = base + (size_t)t * (DIM/4);
        float4 f  = Yf4[off];
        float4 yi = Yi4[off];
        h.x = fmaf(f.x, h.x, (1.f - f.x) * yi.x);
        h.y = fmaf(f.y, h.y, (1.f - f.y) * yi.y);
        h.z = fmaf(f.z, h.z, (1.f - f.z) * yi.z);
        h.w = fmaf(f.w, h.w, (1.f - f.w) * yi.w);

        // block reduce sum(h^2): warp shuffle -> parity smem slot -> one barrier
        float ss = h.x*h.x + h.y*h.y + h.z*h.z + h.w*h.w;
        #pragma unroll
        for (int o = 16; o; o >>= 1) ss += __shfl_xor_sync(0xffffffffu, ss, o);
        if (lane == 0) red[t & 1][wid] = ss;
        __syncthreads();
        float tot = 0.f;
        #pragma unroll
        for (int u = 0; u < 16; u++) tot += red[t & 1][u];
        float rms = rsqrtf(tot * (1.f / DIM) + 1e-5f);

        float4 gv = Yg4[off];          // already g*sigmoid(g)
        float q[4];
        q[0] = h.x * rms * cs.x * gv.x;
        q[1] = h.y * rms * cs.y * gv.y;
        q[2] = h.z * rms * cs.z * gv.z;
        q[3] = h.w * rms * cs.w * gv.w;
        __half hi[4]; __half lo[4];
        #pragma unroll
        for (int u = 0; u < 4; u++) {
            hi[u] = __float2half_rn(q[u]);
            lo[u] = __float2half_rn(q[u] - __half2float(hi[u]));
        }
        size_t m = (size_t)(b * SEQ + c * CHLEN + t);
        ((uint2*)(g_A2 + m * (2*DIM)))[d4]       = *(uint2*)hi;
        ((uint2*)(g_A2 + m * (2*DIM) + DIM))[d4] = *(uint2*)lo;
    }
}

// ---------------- launch ----------------
extern "C" void kernel_launch(void* const* d_in, const int* in_sizes, int n_in,
                              void* d_out, int out_size) {
    const float* hs  = (const float*)d_in[0];
    const float* wi  = (const float*)d_in[1];
    const float* wf  = (const float*)d_in[2];
    const float* wg  = (const float*)d_in[3];
    const float* wo  = (const float*)d_in[4];
    const float* si  = (const float*)d_in[5];
    const float* sf  = (const float*)d_in[6];
    const float* sg  = (const float*)d_in[7];
    const float* so  = (const float*)d_in[8];
    const float* gnw = (const float*)d_in[9];

    __half *Xq, *Wi, *Wf, *Wg, *Wo, *A2;
    float  *Yi, *Yf, *Yg;
    cudaGetSymbolAddress((void**)&Xq,  g_Xq);
    cudaGetSymbolAddress((void**)&Wi,  g_Wi);
    cudaGetSymbolAddress((void**)&Wf,  g_Wf);
    cudaGetSymbolAddress((void**)&Wg,  g_Wg);
    cudaGetSymbolAddress((void**)&Wo,  g_Wo);
    cudaGetSymbolAddress((void**)&A2,  g_A2);
    cudaGetSymbolAddress((void**)&Yi,  g_Yi);
    cudaGetSymbolAddress((void**)&Yf,  g_Yf);
    cudaGetSymbolAddress((void**)&Yg,  g_Yg);

    const int smem = NSTAGE * (BM * BK + BN * BK) * 2;  // 96 KB
    cudaFuncSetAttribute(k_gemm, cudaFuncAttributeMaxDynamicSharedMemorySize, smem);
    cudaFuncSetAttribute((const void*)&k_gemm2<2*DIM, DIM>,
                         cudaFuncAttributeMaxDynamicSharedMemorySize, smem);

    k_quant<<<(M_TOT * DIM) / 1024, 256>>>(hs);
    k_prepw<<<dim3(DIM / 32, DIM / 32, 4), dim3(32, 8)>>>(wi, wf, wg, wo);

    // i/f/g projections: exact integer fp16 MMA; epilogue applies scale + sigmoid/swish
    k_gemm<<<dim3(DIM / BN, M_TOT / BM, 3), NTHREADS, smem>>>(
        Xq, Wi, Wf, Wg, Yi, Yf, Yg, si, sf, sg, DIM, 0);

    k_scan1<<<dim3(DIM / 512, NCH, BATCH), 128>>>();
    k_scan2<<<(BATCH * DIM / 4) / 256, 256>>>();
    k_scan3norm<<<dim3(NCH, BATCH), 512>>>(so, gnw);

    // output projection: split-fp16 (hi+lo), K_eff=4096 over single Wo copy, to_fixed epilogue
    k_gemm2<2*DIM, DIM><<<dim3(DIM / BN, M_TOT / BM), NTHREADS, smem>>>(
        A2, Wo, (float*)d_out);
}

// round 16
// speedup vs baseline: 1.0903x; 1.0091x over previous
#include <cuda_runtime.h>
#include <cuda_fp16.h>
#include <cstdint>

#define BATCH 4
#define SEQ   2048
#define DIM   2048
#define M_TOT (BATCH*SEQ)     // 8192
#define NCH   128
#define CHLEN (SEQ/NCH)       // 16

#define BM 128
#define BN 128
#define BK 64
#define NSTAGE 3
#define NTHREADS 128          // 4 warps, 2x2 grid of 64x64 warp tiles

// ---------------- scratch (device globals; no allocation allowed) ----------------
__device__ __align__(16) __half g_Xq [M_TOT*DIM];        // quantized x (integer k as fp16)
__device__ __align__(16) __half g_Wi [DIM*DIM];          // w_i^T  [N][K]
__device__ __align__(16) __half g_Wf [DIM*DIM];
__device__ __align__(16) __half g_Wg [DIM*DIM];
__device__ __align__(16) __half g_Wo [DIM*DIM];          // w_o fp16 [N][K], single copy
__device__ __align__(16) float  g_Yi [M_TOT*DIM];        // raw i
__device__ __align__(16) float  g_Yf [M_TOT*DIM];        // f = sigmoid(raw)
__device__ __align__(16) float  g_Yg [M_TOT*DIM];        // gsw = g*sigmoid(g)
__device__ __align__(16) __half g_A2 [M_TOT*2*DIM];      // (o*s_o) split hi|lo
__device__ float g_P [NCH*BATCH*DIM];
__device__ float g_Hc[NCH*BATCH*DIM];
__device__ float g_Cr[NCH*BATCH*DIM];

// ---------------- PTX helpers ----------------
__device__ __forceinline__ void cp16(uint32_t s, const void* g) {
    asm volatile("cp.async.cg.shared.global [%0], [%1], 16;\n" :: "r"(s), "l"(g));
}
__device__ __forceinline__ void cp_commit() { asm volatile("cp.async.commit_group;\n"); }
template<int N> __device__ __forceinline__ void cp_wait() {
    asm volatile("cp.async.wait_group %0;\n" :: "n"(N));
}
__device__ __forceinline__ void ldsm4(uint32_t& r0, uint32_t& r1, uint32_t& r2, uint32_t& r3, uint32_t a) {
    asm volatile("ldmatrix.sync.aligned.m8n8.x4.shared.b16 {%0,%1,%2,%3},[%4];\n"
                 : "=r"(r0), "=r"(r1), "=r"(r2), "=r"(r3) : "r"(a));
}
__device__ __forceinline__ void mma16816(float* c, const uint32_t* a, const uint32_t* b) {
    asm volatile("mma.sync.aligned.m16n8k16.row.col.f32.f16.f16.f32 "
                 "{%0,%1,%2,%3},{%4,%5,%6,%7},{%8,%9},{%0,%1,%2,%3};\n"
                 : "+f"(c[0]), "+f"(c[1]), "+f"(c[2]), "+f"(c[3])
                 : "r"(a[0]), "r"(a[1]), "r"(a[2]), "r"(a[3]), "r"(b[0]), "r"(b[1]));
}
// swizzled half-index inside a tile with 64-half rows (rows of 8 chunks of 16B)
__device__ __forceinline__ uint32_t swz(int row, int k) {
    return (uint32_t)(row*BK + ((((k >> 3) ^ (row & 7)) << 3) | (k & 7)));
}
__device__ __forceinline__ float fsig(float x) {   // fast sigmoid via MUFU ex2 path
    return 1.f / (1.f + __expf(-x));
}

// ---------------- elementwise kernels ----------------
__global__ void k_quant(const float* __restrict__ hs) {
    int i = blockIdx.x * 256 + threadIdx.x;
    const float4 v = ((const float4*)hs)[i];
    __half h[4];
    h[0] = __float2half_rn(rintf(v.x * 256.f));
    h[1] = __float2half_rn(rintf(v.y * 256.f));
    h[2] = __float2half_rn(rintf(v.z * 256.f));
    h[3] = __float2half_rn(rintf(v.w * 256.f));
    ((uint2*)g_Xq)[i] = *(uint2*)h;
}

// z<3: transpose+convert w_i/w_f/w_g to [N][K] fp16.  z==3: flat convert w_o.
__global__ void k_prepw(const float* __restrict__ wi, const float* __restrict__ wf,
                        const float* __restrict__ wg, const float* __restrict__ wo) {
    __shared__ float tile[32][33];
    int z = blockIdx.z;
    int tx = threadIdx.x, ty = threadIdx.y;     // 32 x 8
    if (z == 3) {
        int i = (blockIdx.y * 64 + blockIdx.x) * 256 + ty * 32 + tx;   // float4 idx
        const float4 v = ((const float4*)wo)[i];
        __half h[4];
        h[0] = __float2half_rn(v.x);            // ternary: exact
        h[1] = __float2half_rn(v.y);
        h[2] = __float2half_rn(v.z);
        h[3] = __float2half_rn(v.w);
        ((uint2*)g_Wo)[i] = *(uint2*)h;
        return;
    }
    const float* src = (z == 0) ? wi : (z == 1) ? wf : wg;
    __half* dst = (z == 0) ? g_Wi : (z == 1) ? g_Wf : g_Wg;
    int k0 = blockIdx.y * 32, n0 = blockIdx.x * 32;
    #pragma unroll
    for (int j = 0; j < 32; j += 8)
        tile[ty + j][tx] = src[(size_t)(k0 + ty + j) * DIM + n0 + tx];
    __syncthreads();
    #pragma unroll
    for (int j = 0; j < 32; j += 8)
        dst[(size_t)(n0 + ty + j) * DIM + k0 + tx] = __float2half_rn(tile[tx][ty + j]);
}

// ---------------- GEMM1: C[M,N] = A[M,K] * B[N,K]^T (fp16 in, fp32 acc) ----------------
// 4 warps, 64x64 warp tiles, 3-stage cp.async ring.  (R8 known-good schedule — DO NOT TOUCH)
__global__ void __launch_bounds__(NTHREADS, 2) k_gemm(
    const __half* __restrict__ A,
    const __half* __restrict__ B0, const __half* __restrict__ B1,
    const __half* __restrict__ B2,
    float* C0, float* C1, float* C2,
    const float* s0, const float* s1, const float* s2,
    int K, int mode)
{
    extern __shared__ __half sm[];
    constexpr int STAGE_H = BM * BK + BN * BK;    // halfs per stage
    int z = blockIdx.z;
    const __half* Bw = (z == 0) ? B0 : (z == 1) ? B1 : B2;
    float* Cc        = (z == 0) ? C0 : (z == 1) ? C1 : C2;
    const float* sp  = (z == 0) ? s0 : (z == 1) ? s1 : s2;

    int bm = blockIdx.y * BM, bn = blockIdx.x * BN;
    const __half* Ag = A  + (size_t)bm * K;
    const __half* Bg = Bw + (size_t)bn * K;
    int tid = threadIdx.x;
    uint32_t sbase = (uint32_t)__cvta_generic_to_shared(sm);
    int KT = K / BK;

    int lane = tid & 31, w = tid >> 5;
    int wm = (w >> 1) * 64, wn = (w & 1) * 64;   // 2x2 warp grid, warp tile 64x64
    int g = lane >> 2, t2 = (lane & 3) << 1;
    int r = lane & 7, sub = lane >> 3;

    float acc[4][8][4];
    #pragma unroll
    for (int a = 0; a < 4; a++)
        #pragma unroll
        for (int b = 0; b < 8; b++)
            #pragma unroll
            for (int c = 0; c < 4; c++) acc[a][b][c] = 0.f;

    // stage loader: 128 threads, 8 x 16B each for A and B
    auto load = [&](int st, int kt) {
        int kb = kt * BK;
        uint32_t sA = sbase + (uint32_t)(st * STAGE_H) * 2;
        uint32_t sB = sA + (uint32_t)(BM * BK) * 2;
        #pragma unroll
        for (int i = 0; i < 8; i++) {
            int v = tid + i * NTHREADS;
            int row = v >> 3, ch = v & 7;
            uint32_t so = (uint32_t)(swz(row, ch * 8) * 2);
            cp16(sA + so, Ag + (size_t)row * K + kb + ch * 8);
            cp16(sB + so, Bg + (size_t)row * K + kb + ch * 8);
        }
    };

    // prologue: fill NSTAGE-1 stages
    load(0, 0); cp_commit();
    load(1, 1); cp_commit();

    for (int kt = 0; kt < KT; kt++) {
        cp_wait<NSTAGE - 2>();       // stage kt resident
        __syncthreads();
        if (kt + NSTAGE - 1 < KT) load((kt + NSTAGE - 1) % NSTAGE, kt + NSTAGE - 1);
        cp_commit();                 // uniform group counting

        int stb = (kt % NSTAGE) * STAGE_H;
        uint32_t sA = sbase + (uint32_t)stb * 2;
        uint32_t sB = sA + (uint32_t)(BM * BK) * 2;
        #pragma unroll
        for (int ks = 0; ks < 4; ks++) {
            int ko = ks * 16;
            uint32_t a[4][4], b[8][2];
            #pragma unroll
            for (int mi = 0; mi < 4; mi++) {
                int row = wm + mi * 16 + r + ((sub & 1) << 3);
                int kk  = ko + ((sub >> 1) << 3);
                ldsm4(a[mi][0], a[mi][1], a[mi][2], a[mi][3],
                      sA + (uint32_t)(swz(row, kk) * 2));
            }
            #pragma unroll
            for (int p = 0; p < 4; p++) {
                int rown = wn + p * 16 + r + ((sub >> 1) << 3);
                int kk   = ko + ((sub & 1) << 3);
                ldsm4(b[2*p][0], b[2*p][1], b[2*p+1][0], b[2*p+1][1],
                      sB + (uint32_t)(swz(rown, kk) * 2));
            }
            #pragma unroll
            for (int mi = 0; mi < 4; mi++)
                #pragma unroll
                for (int ni = 0; ni < 8; ni++)
                    mma16816(acc[mi][ni], a[mi], b[ni]);
        }
    }

    const float inv256 = 1.f / 256.f;
    #pragma unroll
    for (int mi = 0; mi < 4; mi++) {
        #pragma unroll
        for (int ni = 0; ni < 8; ni++) {
            int row = bm + wm + mi * 16 + g;
            int col = bn + wn + ni * 8 + t2;
            float* c = acc[mi][ni];
            if (mode == 0) {
                float sa = sp[col] * inv256, sb = sp[col + 1] * inv256;
                float v0 = c[0] * sa, v1 = c[1] * sb, v2 = c[2] * sa, v3 = c[3] * sb;
                if (z == 1) {          // forget gate: store sigmoid
                    v0 = fsig(v0); v1 = fsig(v1); v2 = fsig(v2); v3 = fsig(v3);
                } else if (z == 2) {   // output gate: store swish
                    v0 = v0 * fsig(v0); v1 = v1 * fsig(v1);
                    v2 = v2 * fsig(v2); v3 = v3 * fsig(v3);
                }
                Cc[(size_t)row * DIM + col]           = v0;
                Cc[(size_t)row * DIM + col + 1]       = v1;
                Cc[(size_t)(row + 8) * DIM + col]     = v2;
                Cc[(size_t)(row + 8) * DIM + col + 1] = v3;
            } else {  // to_fixed(acc)
                Cc[(size_t)row * DIM + col]           = rintf(c[0] * 256.f) * inv256;
                Cc[(size_t)row * DIM + col + 1]       = rintf(c[1] * 256.f) * inv256;
                Cc[(size_t)(row + 8) * DIM + col]     = rintf(c[2] * 256.f) * inv256;
                Cc[(size_t)(row + 8) * DIM + col + 1] = rintf(c[3] * 256.f) * inv256;
            }
        }
    }
}

// ---------------- GEMM2: out = to_fixed(A[M,4096] * Wo[N,2048]^T dup over K) ----------------
// BM2=64 tiles (2048 CTAs -> 6.92 waves at 296 slots, ~1% quantization loss).
// 4 warps, 32x64 warp tiles, 3-stage ring. B k-index = k & (KB-1).
template<int K, int KB>
__global__ void __launch_bounds__(NTHREADS, 2) k_gemm2(
    const __half* __restrict__ A, const __half* __restrict__ Bw, float* __restrict__ Cc)
{
    constexpr int BM2 = 64;
    extern __shared__ __half sm[];
    constexpr int STAGE_H = BM2 * BK + BN * BK;   // 12288 halfs = 24 KB
    constexpr int KT = K / BK;

    int bm = blockIdx.y * BM2, bn = blockIdx.x * BN;
    const __half* Ag = A  + (size_t)bm * K;
    const __half* Bg = Bw + (size_t)bn * KB;
    int tid = threadIdx.x;
    uint32_t sbase = (uint32_t)__cvta_generic_to_shared(sm);

    int lane = tid & 31, w = tid >> 5;
    int wm = (w >> 1) * 32, wn = (w & 1) * 64;   // 2x2 warp grid, warp tile 32x64
    int g = lane >> 2, t2 = (lane & 3) << 1;
    int r = lane & 7, sub = lane >> 3;

    float acc[2][8][4];
    #pragma unroll
    for (int a = 0; a < 2; a++)
        #pragma unroll
        for (int b = 0; b < 8; b++)
            #pragma unroll
            for (int c = 0; c < 4; c++) acc[a][b][c] = 0.f;

    // stage loader: A 64 rows (4 x 16B/thread), B 128 rows (8 x 16B/thread)
    auto load = [&](int st, int kt) {
        int kb = kt * BK;
        int kbb = kb & (KB - 1);
        uint32_t sA = sbase + (uint32_t)(st * STAGE_H) * 2;
        uint32_t sB = sA + (uint32_t)(BM2 * BK) * 2;
        #pragma unroll
        for (int i = 0; i < 4; i++) {
            int v = tid + i * NTHREADS;
            int row = v >> 3, ch = v & 7;
            cp16(sA + (uint32_t)(swz(row, ch * 8) * 2), Ag + (size_t)row * K + kb + ch * 8);
        }
        #pragma unroll
        for (int i = 0; i < 8; i++) {
            int v = tid + i * NTHREADS;
            int row = v >> 3, ch = v & 7;
            cp16(sB + (uint32_t)(swz(row, ch * 8) * 2), Bg + (size_t)row * KB + kbb + ch * 8);
        }
    };

    load(0, 0); cp_commit();
    load(1, 1); cp_commit();

    for (int kt = 0; kt < KT; kt++) {
        cp_wait<NSTAGE - 2>();
        __syncthreads();
        if (kt + NSTAGE - 1 < KT) load((kt + NSTAGE - 1) % NSTAGE, kt + NSTAGE - 1);
        cp_commit();

        int stb = (kt % NSTAGE) * STAGE_H;
        uint32_t sA = sbase + (uint32_t)stb * 2;
        uint32_t sB = sA + (uint32_t)(BM2 * BK) * 2;
        #pragma unroll
        for (int ks = 0; ks < 4; ks++) {
            int ko = ks * 16;
            uint32_t a[2][4], b[8][2];
            #pragma unroll
            for (int mi = 0; mi < 2; mi++) {
                int row = wm + mi * 16 + r + ((sub & 1) << 3);
                int kk  = ko + ((sub >> 1) << 3);
                ldsm4(a[mi][0], a[mi][1], a[mi][2], a[mi][3],
                      sA + (uint32_t)(swz(row, kk) * 2));
            }
            #pragma unroll
            for (int p = 0; p < 4; p++) {
                int rown = wn + p * 16 + r + ((sub >> 1) << 3);
                int kk   = ko + ((sub & 1) << 3);
                ldsm4(b[2*p][0], b[2*p][1], b[2*p+1][0], b[2*p+1][1],
                      sB + (uint32_t)(swz(rown, kk) * 2));
            }
            #pragma unroll
            for (int mi = 0; mi < 2; mi++)
                #pragma unroll
                for (int ni = 0; ni < 8; ni++)
                    mma16816(acc[mi][ni], a[mi], b[ni]);
        }
    }

    const float inv256 = 1.f / 256.f;
    #pragma unroll
    for (int mi = 0; mi < 2; mi++) {
        #pragma unroll
        for (int ni = 0; ni < 8; ni++) {
            int row = bm + wm + mi * 16 + g;
            int col = bn + wn + ni * 8 + t2;
            float* c = acc[mi][ni];
            Cc[(size_t)row * DIM + col]           = rintf(c[0] * 256.f) * inv256;
            Cc[(size_t)row * DIM + col + 1]       = rintf(c[1] * 256.f) * inv256;
            Cc[(size_t)(row + 8) * DIM + col]     = rintf(c[2] * 256.f) * inv256;
            Cc[(size_t)(row + 8) * DIM + col + 1] = rintf(c[3] * 256.f) * inv256;
        }
    }
}

// ---------------- chunked linear-recurrence scan (f precomputed) ----------------
__global__ void k_scan1() {
    int d4 = blockIdx.x * 128 + threadIdx.x;        // float4 index within DIM/4
    int c = blockIdx.y, b = blockIdx.z;
    size_t base = ((size_t)(b * SEQ + c * CHLEN)) * (DIM/4) + d4;
    const float4* Yf4 = (const float4*)g_Yf;
    const float4* Yi4 = (const float4*)g_Yi;
    float4 P = make_float4(1.f,1.f,1.f,1.f), H = make_float4(0.f,0.f,0.f,0.f);
    #pragma unroll
    for (int t = 0; t < CHLEN; t++) {
        float4 f  = Yf4[base + (size_t)t * (DIM/4)];
        float4 yi = Yi4[base + (size_t)t * (DIM/4)];
        P.x *= f.x; P.y *= f.y; P.z *= f.z; P.w *= f.w;
        H.x = fmaf(f.x, H.x, (1.f - f.x) * yi.x);
        H.y = fmaf(f.y, H.y, (1.f - f.y) * yi.y);
        H.z = fmaf(f.z, H.z, (1.f - f.z) * yi.z);
        H.w = fmaf(f.w, H.w, (1.f - f.w) * yi.w);
    }
    int o = (c * BATCH + b) * (DIM/4) + d4;
    ((float4*)g_P)[o] = P; ((float4*)g_Hc)[o] = H;
}

__global__ void k_scan2() {
    int idx = blockIdx.x * 256 + threadIdx.x;   // 0..B*DIM/4-1
    float4 h = make_float4(0.f,0.f,0.f,0.f);
    #pragma unroll 8
    for (int c = 0; c < NCH; c++) {
        int o = c * (BATCH * DIM / 4) + idx;
        ((float4*)g_Cr)[o] = h;
        float4 P = ((const float4*)g_P)[o];
        float4 Hc = ((const float4*)g_Hc)[o];
        h.x = fmaf(P.x, h.x, Hc.x); h.y = fmaf(P.y, h.y, Hc.y);
        h.z = fmaf(P.z, h.z, Hc.z); h.w = fmaf(P.w, h.w, Hc.w);
    }
}

// ---------------- fused finalize-scan + RMSNorm + gate + hi/lo split ----------------
// One CTA per (chunk, batch): 512 threads cover full DIM (4 dims/thread).
// Single __syncthreads per t-step via parity-double-buffered partials.
__global__ void __launch_bounds__(512, 2) k_scan3norm(
    const float* __restrict__ so, const float* __restrict__ gnw)
{
    int c = blockIdx.x, b = blockIdx.y;
    int d4 = threadIdx.x;                         // 0..511, covers dims 4*d4..4*d4+3
    int lane = d4 & 31, wid = d4 >> 5;
    size_t base = ((size_t)(b * SEQ + c * CHLEN)) * (DIM/4) + d4;
    const float4* Yf4 = (const float4*)g_Yf;
    const float4* Yi4 = (const float4*)g_Yi;
    const float4* Yg4 = (const float4*)g_Yg;

    float4 sv = ((const float4*)so)[d4];
    float4 wv = ((const float4*)gnw)[d4];
    float4 cs = make_float4(wv.x * sv.x, wv.y * sv.y, wv.z * sv.z, wv.w * sv.w);

    float4 h = ((const float4*)g_Cr)[(c * BATCH + b) * (DIM/4) + d4];

    __shared__ float red[2][16];

    for (int t = 0; t < CHLEN; t++) {
        size_t off = base + (size_t)t * (DIM/4);
        float4 f  = Yf4[off];
        float4 yi = Yi4[off];
        h.x = fmaf(f.x, h.x, (1.f - f.x) * yi.x);
        h.y = fmaf(f.y, h.y, (1.f - f.y) * yi.y);
        h.z = fmaf(f.z, h.z, (1.f - f.z) * yi.z);
        h.w = fmaf(f.w, h.w, (1.f - f.w) * yi.w);

        // block reduce sum(h^2): warp shuffle -> parity smem slot -> one barrier
        float ss = h.x*h.x + h.y*h.y + h.z*h.z + h.w*h.w;
        #pragma unroll
        for (int o = 16; o; o >>= 1) ss += __shfl_xor_sync(0xffffffffu, ss, o);
        if (lane == 0) red[t & 1][wid] = ss;
        __syncthreads();
        float tot = 0.f;
        #pragma unroll
        for (int u = 0; u < 16; u++) tot += red[t & 1][u];
        float rms = rsqrtf(tot * (1.f / DIM) + 1e-5f);

        float4 gv = Yg4[off];          // already g*sigmoid(g)
        float q[4];
        q[0] = h.x * rms * cs.x * gv.x;
        q[1] = h.y * rms * cs.y * gv.y;
        q[2] = h.z * rms * cs.z * gv.z;
        q[3] = h.w * rms * cs.w * gv.w;
        __half hi[4]; __half lo[4];
        #pragma unroll
        for (int u = 0; u < 4; u++) {
            hi[u] = __float2half_rn(q[u]);
            lo[u] = __float2half_rn(q[u] - __half2float(hi[u]));
        }
        size_t m = (size_t)(b * SEQ + c * CHLEN + t);
        ((uint2*)(g_A2 + m * (2*DIM)))[d4]       = *(uint2*)hi;
        ((uint2*)(g_A2 + m * (2*DIM) + DIM))[d4] = *(uint2*)lo;
    }
}

// ---------------- launch ----------------
extern "C" void kernel_launch(void* const* d_in, const int* in_sizes, int n_in,
                              void* d_out, int out_size) {
    const float* hs  = (const float*)d_in[0];
    const float* wi  = (const float*)d_in[1];
    const float* wf  = (const float*)d_in[2];
    const float* wg  = (const float*)d_in[3];
    const float* wo  = (const float*)d_in[4];
    const float* si  = (const float*)d_in[5];
    const float* sf  = (const float*)d_in[6];
    const float* sg  = (const float*)d_in[7];
    const float* so  = (const float*)d_in[8];
    const float* gnw = (const float*)d_in[9];

    __half *Xq, *Wi, *Wf, *Wg, *Wo, *A2;
    float  *Yi, *Yf, *Yg;
    cudaGetSymbolAddress((void**)&Xq,  g_Xq);
    cudaGetSymbolAddress((void**)&Wi,  g_Wi);
    cudaGetSymbolAddress((void**)&Wf,  g_Wf);
    cudaGetSymbolAddress((void**)&Wg,  g_Wg);
    cudaGetSymbolAddress((void**)&Wo,  g_Wo);
    cudaGetSymbolAddress((void**)&A2,  g_A2);
    cudaGetSymbolAddress((void**)&Yi,  g_Yi);
    cudaGetSymbolAddress((void**)&Yf,  g_Yf);
    cudaGetSymbolAddress((void**)&Yg,  g_Yg);

    const int smem = NSTAGE * (BM * BK + BN * BK) * 2;  // 96 KB
    cudaFuncSetAttribute(k_gemm, cudaFuncAttributeMaxDynamicSharedMemorySize, smem);
    // GEMM2 uses only 72 KB but we request 96 KB to pin occupancy at exactly
    // 2 CTAs/SM (3/SM would give a worse 4.61->5 wave quantization).
    cudaFuncSetAttribute((const void*)&k_gemm2<2*DIM, DIM>,
                         cudaFuncAttributeMaxDynamicSharedMemorySize, smem);

    k_quant<<<(M_TOT * DIM) / 1024, 256>>>(hs);
    k_prepw<<<dim3(DIM / 32, DIM / 32, 4), dim3(32, 8)>>>(wi, wf, wg, wo);

    // i/f/g projections: exact integer fp16 MMA; epilogue applies scale + sigmoid/swish
    k_gemm<<<dim3(DIM / BN, M_TOT / BM, 3), NTHREADS, smem>>>(
        Xq, Wi, Wf, Wg, Yi, Yf, Yg, si, sf, sg, DIM, 0);

    k_scan1<<<dim3(DIM / 512, NCH, BATCH), 128>>>();
    k_scan2<<<(BATCH * DIM / 4) / 256, 256>>>();
    k_scan3norm<<<dim3(NCH, BATCH), 512>>>(so, gnw);

    // output projection: split-fp16 (hi+lo), K_eff=4096 over single Wo copy,
    // BM=64 tiles for fine-grained wave packing, to_fixed epilogue
    k_gemm2<2*DIM, DIM><<<dim3(DIM / BN, M_TOT / 64), NTHREADS, smem>>>(
        A2, Wo, (float*)d_out);
}

// round 17
// speedup vs baseline: 1.1004x; 1.0093x over previous
#include <cuda_runtime.h>
#include <cuda_fp16.h>
#include <cstdint>

#define BATCH 4
#define SEQ   2048
#define DIM   2048
#define M_TOT (BATCH*SEQ)     // 8192
#define NCH   128
#define CHLEN (SEQ/NCH)       // 16

#define BM 128
#define BN 128
#define BK 64
#define NSTAGE 3
#define NTHREADS 128          // 4 warps, 2x2 grid of 64x64 warp tiles

// ---------------- scratch (device globals; no allocation allowed) ----------------
__device__ __align__(16) __half g_Xq [M_TOT*DIM];        // quantized x (integer k as fp16)
__device__ __align__(16) __half g_Wi [DIM*DIM];          // w_i^T  [N][K]
__device__ __align__(16) __half g_Wf [DIM*DIM];
__device__ __align__(16) __half g_Wg [DIM*DIM];
__device__ __align__(16) __half g_Wo [DIM*DIM];          // w_o fp16 [N][K], single copy
__device__ __align__(16) float  g_Yi [M_TOT*DIM];        // raw i
__device__ __align__(16) float  g_Yf [M_TOT*DIM];        // f = sigmoid(raw)
__device__ __align__(16) float  g_Yg [M_TOT*DIM];        // gsw = g*sigmoid(g)
__device__ __align__(16) __half g_A2 [M_TOT*2*DIM];      // (o*s_o) split hi|lo
__device__ float g_P [NCH*BATCH*DIM];
__device__ float g_Hc[NCH*BATCH*DIM];
__device__ float g_Cr[NCH*BATCH*DIM];

// ---------------- PTX helpers ----------------
__device__ __forceinline__ void cp16(uint32_t s, const void* g) {
    asm volatile("cp.async.cg.shared.global [%0], [%1], 16;\n" :: "r"(s), "l"(g));
}
__device__ __forceinline__ void cp_commit() { asm volatile("cp.async.commit_group;\n"); }
template<int N> __device__ __forceinline__ void cp_wait() {
    asm volatile("cp.async.wait_group %0;\n" :: "n"(N));
}
__device__ __forceinline__ void ldsm4(uint32_t& r0, uint32_t& r1, uint32_t& r2, uint32_t& r3, uint32_t a) {
    asm volatile("ldmatrix.sync.aligned.m8n8.x4.shared.b16 {%0,%1,%2,%3},[%4];\n"
                 : "=r"(r0), "=r"(r1), "=r"(r2), "=r"(r3) : "r"(a));
}
__device__ __forceinline__ void mma16816(float* c, const uint32_t* a, const uint32_t* b) {
    asm volatile("mma.sync.aligned.m16n8k16.row.col.f32.f16.f16.f32 "
                 "{%0,%1,%2,%3},{%4,%5,%6,%7},{%8,%9},{%0,%1,%2,%3};\n"
                 : "+f"(c[0]), "+f"(c[1]), "+f"(c[2]), "+f"(c[3])
                 : "r"(a[0]), "r"(a[1]), "r"(a[2]), "r"(a[3]), "r"(b[0]), "r"(b[1]));
}
// swizzled half-index inside a tile with 64-half rows (rows of 8 chunks of 16B)
__device__ __forceinline__ uint32_t swz(int row, int k) {
    return (uint32_t)(row*BK + ((((k >> 3) ^ (row & 7)) << 3) | (k & 7)));
}
__device__ __forceinline__ float fsig(float x) {   // fast sigmoid via MUFU ex2 path
    return 1.f / (1.f + __expf(-x));
}

// ---------------- elementwise kernels ----------------
__global__ void k_quant(const float* __restrict__ hs) {
    int i = blockIdx.x * 256 + threadIdx.x;
    const float4 v = ((const float4*)hs)[i];
    __half h[4];
    h[0] = __float2half_rn(rintf(v.x * 256.f));
    h[1] = __float2half_rn(rintf(v.y * 256.f));
    h[2] = __float2half_rn(rintf(v.z * 256.f));
    h[3] = __float2half_rn(rintf(v.w * 256.f));
    ((uint2*)g_Xq)[i] = *(uint2*)h;
}

// z<3: transpose+convert w_i/w_f/w_g to [N][K] fp16.  z==3: flat convert w_o.
__global__ void k_prepw(const float* __restrict__ wi, const float* __restrict__ wf,
                        const float* __restrict__ wg, const float* __restrict__ wo) {
    __shared__ float tile[32][33];
    int z = blockIdx.z;
    int tx = threadIdx.x, ty = threadIdx.y;     // 32 x 8
    if (z == 3) {
        int i = (blockIdx.y * 64 + blockIdx.x) * 256 + ty * 32 + tx;   // float4 idx
        const float4 v = ((const float4*)wo)[i];
        __half h[4];
        h[0] = __float2half_rn(v.x);            // ternary: exact
        h[1] = __float2half_rn(v.y);
        h[2] = __float2half_rn(v.z);
        h[3] = __float2half_rn(v.w);
        ((uint2*)g_Wo)[i] = *(uint2*)h;
        return;
    }
    const float* src = (z == 0) ? wi : (z == 1) ? wf : wg;
    __half* dst = (z == 0) ? g_Wi : (z == 1) ? g_Wf : g_Wg;
    int k0 = blockIdx.y * 32, n0 = blockIdx.x * 32;
    #pragma unroll
    for (int j = 0; j < 32; j += 8)
        tile[ty + j][tx] = src[(size_t)(k0 + ty + j) * DIM + n0 + tx];
    __syncthreads();
    #pragma unroll
    for (int j = 0; j < 32; j += 8)
        dst[(size_t)(n0 + ty + j) * DIM + k0 + tx] = __float2half_rn(tile[tx][ty + j]);
}

// ---------------- GEMM1: C[M,N] = A[M,K] * B[N,K]^T (fp16 in, fp32 acc) ----------------
// 4 warps, 64x64 warp tiles, 3-stage cp.async ring.  (R8 known-good schedule — DO NOT TOUCH)
__global__ void __launch_bounds__(NTHREADS, 2) k_gemm(
    const __half* __restrict__ A,
    const __half* __restrict__ B0, const __half* __restrict__ B1,
    const __half* __restrict__ B2,
    float* C0, float* C1, float* C2,
    const float* s0, const float* s1, const float* s2,
    int K, int mode)
{
    extern __shared__ __half sm[];
    constexpr int STAGE_H = BM * BK + BN * BK;    // halfs per stage
    int z = blockIdx.z;
    const __half* Bw = (z == 0) ? B0 : (z == 1) ? B1 : B2;
    float* Cc        = (z == 0) ? C0 : (z == 1) ? C1 : C2;
    const float* sp  = (z == 0) ? s0 : (z == 1) ? s1 : s2;

    int bm = blockIdx.y * BM, bn = blockIdx.x * BN;
    const __half* Ag = A  + (size_t)bm * K;
    const __half* Bg = Bw + (size_t)bn * K;
    int tid = threadIdx.x;
    uint32_t sbase = (uint32_t)__cvta_generic_to_shared(sm);
    int KT = K / BK;

    int lane = tid & 31, w = tid >> 5;
    int wm = (w >> 1) * 64, wn = (w & 1) * 64;   // 2x2 warp grid, warp tile 64x64
    int g = lane >> 2, t2 = (lane & 3) << 1;
    int r = lane & 7, sub = lane >> 3;

    float acc[4][8][4];
    #pragma unroll
    for (int a = 0; a < 4; a++)
        #pragma unroll
        for (int b = 0; b < 8; b++)
            #pragma unroll
            for (int c = 0; c < 4; c++) acc[a][b][c] = 0.f;

    // stage loader: 128 threads, 8 x 16B each for A and B
    auto load = [&](int st, int kt) {
        int kb = kt * BK;
        uint32_t sA = sbase + (uint32_t)(st * STAGE_H) * 2;
        uint32_t sB = sA + (uint32_t)(BM * BK) * 2;
        #pragma unroll
        for (int i = 0; i < 8; i++) {
            int v = tid + i * NTHREADS;
            int row = v >> 3, ch = v & 7;
            uint32_t so = (uint32_t)(swz(row, ch * 8) * 2);
            cp16(sA + so, Ag + (size_t)row * K + kb + ch * 8);
            cp16(sB + so, Bg + (size_t)row * K + kb + ch * 8);
        }
    };

    // prologue: fill NSTAGE-1 stages
    load(0, 0); cp_commit();
    load(1, 1); cp_commit();

    for (int kt = 0; kt < KT; kt++) {
        cp_wait<NSTAGE - 2>();       // stage kt resident
        __syncthreads();
        if (kt + NSTAGE - 1 < KT) load((kt + NSTAGE - 1) % NSTAGE, kt + NSTAGE - 1);
        cp_commit();                 // uniform group counting

        int stb = (kt % NSTAGE) * STAGE_H;
        uint32_t sA = sbase + (uint32_t)stb * 2;
        uint32_t sB = sA + (uint32_t)(BM * BK) * 2;
        #pragma unroll
        for (int ks = 0; ks < 4; ks++) {
            int ko = ks * 16;
            uint32_t a[4][4], b[8][2];
            #pragma unroll
            for (int mi = 0; mi < 4; mi++) {
                int row = wm + mi * 16 + r + ((sub & 1) << 3);
                int kk  = ko + ((sub >> 1) << 3);
                ldsm4(a[mi][0], a[mi][1], a[mi][2], a[mi][3],
                      sA + (uint32_t)(swz(row, kk) * 2));
            }
            #pragma unroll
            for (int p = 0; p < 4; p++) {
                int rown = wn + p * 16 + r + ((sub >> 1) << 3);
                int kk   = ko + ((sub & 1) << 3);
                ldsm4(b[2*p][0], b[2*p][1], b[2*p+1][0], b[2*p+1][1],
                      sB + (uint32_t)(swz(rown, kk) * 2));
            }
            #pragma unroll
            for (int mi = 0; mi < 4; mi++)
                #pragma unroll
                for (int ni = 0; ni < 8; ni++)
                    mma16816(acc[mi][ni], a[mi], b[ni]);
        }
    }

    const float inv256 = 1.f / 256.f;
    #pragma unroll
    for (int mi = 0; mi < 4; mi++) {
        #pragma unroll
        for (int ni = 0; ni < 8; ni++) {
            int row = bm + wm + mi * 16 + g;
            int col = bn + wn + ni * 8 + t2;
            float* c = acc[mi][ni];
            if (mode == 0) {
                float sa = sp[col] * inv256, sb = sp[col + 1] * inv256;
                float v0 = c[0] * sa, v1 = c[1] * sb, v2 = c[2] * sa, v3 = c[3] * sb;
                if (z == 1) {          // forget gate: store sigmoid
                    v0 = fsig(v0); v1 = fsig(v1); v2 = fsig(v2); v3 = fsig(v3);
                } else if (z == 2) {   // output gate: store swish
                    v0 = v0 * fsig(v0); v1 = v1 * fsig(v1);
                    v2 = v2 * fsig(v2); v3 = v3 * fsig(v3);
                }
                Cc[(size_t)row * DIM + col]           = v0;
                Cc[(size_t)row * DIM + col + 1]       = v1;
                Cc[(size_t)(row + 8) * DIM + col]     = v2;
                Cc[(size_t)(row + 8) * DIM + col + 1] = v3;
            } else {  // to_fixed(acc)
                Cc[(size_t)row * DIM + col]           = rintf(c[0] * 256.f) * inv256;
                Cc[(size_t)row * DIM + col + 1]       = rintf(c[1] * 256.f) * inv256;
                Cc[(size_t)(row + 8) * DIM + col]     = rintf(c[2] * 256.f) * inv256;
                Cc[(size_t)(row + 8) * DIM + col + 1] = rintf(c[3] * 256.f) * inv256;
            }
        }
    }
}

// ---------------- GEMM2: out = to_fixed(A_hi*Wo^T + A_lo*Wo^T) ----------------
// BM2=64 tiles (2048 CTAs, ~1% wave quantization). hi/lo K-pairs share ONE B
// stage load: stage = A_hi(8KB) + A_lo(8KB) + B(16KB) = 32KB, 3 stages = 96KB.
// Per ks: 8 ldsm feed 32 mma (ratio 0.25). AS = A row stride (4096).
template<int AS>
__global__ void __launch_bounds__(NTHREADS, 2) k_gemm2(
    const __half* __restrict__ A, const __half* __restrict__ Bw, float* __restrict__ Cc)
{
    constexpr int BM2 = 64;
    extern __shared__ __half sm[];
    constexpr int A_H  = BM2 * BK;                // 4096 halfs per A tile
    constexpr int STAGE_H = 2 * A_H + BN * BK;    // 16384 halfs = 32 KB
    constexpr int KT = DIM / BK;                  // 32 k-pair iterations

    int bm = blockIdx.y * BM2, bn = blockIdx.x * BN;
    const __half* Ag = A  + (size_t)bm * AS;
    const __half* Bg = Bw + (size_t)bn * DIM;
    int tid = threadIdx.x;
    uint32_t sbase = (uint32_t)__cvta_generic_to_shared(sm);

    int lane = tid & 31, w = tid >> 5;
    int wm = (w >> 1) * 32, wn = (w & 1) * 64;   // 2x2 warp grid, warp tile 32x64
    int g = lane >> 2, t2 = (lane & 3) << 1;
    int r = lane & 7, sub = lane >> 3;

    float acc[2][8][4];
    #pragma unroll
    for (int a = 0; a < 2; a++)
        #pragma unroll
        for (int b = 0; b < 8; b++)
            #pragma unroll
            for (int c = 0; c < 4; c++) acc[a][b][c] = 0.f;

    // stage loader: A_hi 4 x 16B/thread, A_lo 4 x, B 8 x
    auto load = [&](int st, int kt) {
        int kb = kt * BK;
        uint32_t sA = sbase + (uint32_t)(st * STAGE_H) * 2;
        uint32_t sL = sA + (uint32_t)A_H * 2;
        uint32_t sB = sA + (uint32_t)(2 * A_H) * 2;
        #pragma unroll
        for (int i = 0; i < 4; i++) {
            int v = tid + i * NTHREADS;
            int row = v >> 3, ch = v & 7;
            uint32_t so = (uint32_t)(swz(row, ch * 8) * 2);
            cp16(sA + so, Ag + (size_t)row * AS + kb + ch * 8);
            cp16(sL + so, Ag + (size_t)row * AS + DIM + kb + ch * 8);
        }
        #pragma unroll
        for (int i = 0; i < 8; i++) {
            int v = tid + i * NTHREADS;
            int row = v >> 3, ch = v & 7;
            cp16(sB + (uint32_t)(swz(row, ch * 8) * 2), Bg + (size_t)row * DIM + kb + ch * 8);
        }
    };

    load(0, 0); cp_commit();
    load(1, 1); cp_commit();

    for (int kt = 0; kt < KT; kt++) {
        cp_wait<NSTAGE - 2>();
        __syncthreads();
        if (kt + NSTAGE - 1 < KT) load((kt + NSTAGE - 1) % NSTAGE, kt + NSTAGE - 1);
        cp_commit();

        int stb = (kt % NSTAGE) * STAGE_H;
        uint32_t sA = sbase + (uint32_t)stb * 2;
        uint32_t sL = sA + (uint32_t)A_H * 2;
        uint32_t sB = sA + (uint32_t)(2 * A_H) * 2;
        #pragma unroll
        for (int ks = 0; ks < 4; ks++) {
            int ko = ks * 16;
            uint32_t ah[2][4], al[2][4], b[8][2];
            #pragma unroll
            for (int mi = 0; mi < 2; mi++) {
                int row = wm + mi * 16 + r + ((sub & 1) << 3);
                int kk  = ko + ((sub >> 1) << 3);
                uint32_t so = (uint32_t)(swz(row, kk) * 2);
                ldsm4(ah[mi][0], ah[mi][1], ah[mi][2], ah[mi][3], sA + so);
                ldsm4(al[mi][0], al[mi][1], al[mi][2], al[mi][3], sL + so);
            }
            #pragma unroll
            for (int p = 0; p < 4; p++) {
                int rown = wn + p * 16 + r + ((sub >> 1) << 3);
                int kk   = ko + ((sub & 1) << 3);
                ldsm4(b[2*p][0], b[2*p][1], b[2*p+1][0], b[2*p+1][1],
                      sB + (uint32_t)(swz(rown, kk) * 2));
            }
            #pragma unroll
            for (int mi = 0; mi < 2; mi++)
                #pragma unroll
                for (int ni = 0; ni < 8; ni++) {
                    mma16816(acc[mi][ni], ah[mi], b[ni]);
                    mma16816(acc[mi][ni], al[mi], b[ni]);
                }
        }
    }

    const float inv256 = 1.f / 256.f;
    #pragma unroll
    for (int mi = 0; mi < 2; mi++) {
        #pragma unroll
        for (int ni = 0; ni < 8; ni++) {
            int row = bm + wm + mi * 16 + g;
            int col = bn + wn + ni * 8 + t2;
            float* c = acc[mi][ni];
            Cc[(size_t)row * DIM + col]           = rintf(c[0] * 256.f) * inv256;
            Cc[(size_t)row * DIM + col + 1]       = rintf(c[1] * 256.f) * inv256;
            Cc[(size_t)(row + 8) * DIM + col]     = rintf(c[2] * 256.f) * inv256;
            Cc[(size_t)(row + 8) * DIM + col + 1] = rintf(c[3] * 256.f) * inv256;
        }
    }
}

// ---------------- chunked linear-recurrence scan (f precomputed) ----------------
__global__ void k_scan1() {
    int d4 = blockIdx.x * 128 + threadIdx.x;        // float4 index within DIM/4
    int c = blockIdx.y, b = blockIdx.z;
    size_t base = ((size_t)(b * SEQ + c * CHLEN)) * (DIM/4) + d4;
    const float4* Yf4 = (const float4*)g_Yf;
    const float4* Yi4 = (const float4*)g_Yi;
    float4 P = make_float4(1.f,1.f,1.f,1.f), H = make_float4(0.f,0.f,0.f,0.f);
    #pragma unroll
    for (int t = 0; t < CHLEN; t++) {
        float4 f  = Yf4[base + (size_t)t * (DIM/4)];
        float4 yi = Yi4[base + (size_t)t * (DIM/4)];
        P.x *= f.x; P.y *= f.y; P.z *= f.z; P.w *= f.w;
        H.x = fmaf(f.x, H.x, (1.f - f.x) * yi.x);
        H.y = fmaf(f.y, H.y, (1.f - f.y) * yi.y);
        H.z = fmaf(f.z, H.z, (1.f - f.z) * yi.z);
        H.w = fmaf(f.w, H.w, (1.f - f.w) * yi.w);
    }
    int o = (c * BATCH + b) * (DIM/4) + d4;
    ((float4*)g_P)[o] = P; ((float4*)g_Hc)[o] = H;
}

__global__ void k_scan2() {
    int idx = blockIdx.x * 256 + threadIdx.x;   // 0..B*DIM/4-1
    float4 h = make_float4(0.f,0.f,0.f,0.f);
    #pragma unroll 8
    for (int c = 0; c < NCH; c++) {
        int o = c * (BATCH * DIM / 4) + idx;
        ((float4*)g_Cr)[o] = h;
        float4 P = ((const float4*)g_P)[o];
        float4 Hc = ((const float4*)g_Hc)[o];
        h.x = fmaf(P.x, h.x, Hc.x); h.y = fmaf(P.y, h.y, Hc.y);
        h.z = fmaf(P.z, h.z, Hc.z); h.w = fmaf(P.w, h.w, Hc.w);
    }
}

// ---------------- fused finalize-scan + RMSNorm + gate + hi/lo split ----------------
// One CTA per (chunk, batch): 512 threads cover full DIM (4 dims/thread).
// Single __syncthreads per t-step via parity-double-buffered partials.
__global__ void __launch_bounds__(512, 2) k_scan3norm(
    const float* __restrict__ so, const float* __restrict__ gnw)
{
    int c = blockIdx.x, b = blockIdx.y;
    int d4 = threadIdx.x;                         // 0..511, covers dims 4*d4..4*d4+3
    int lane = d4 & 31, wid = d4 >> 5;
    size_t base = ((size_t)(b * SEQ + c * CHLEN)) * (DIM/4) + d4;
    const float4* Yf4 = (const float4*)g_Yf;
    const float4* Yi4 = (const float4*)g_Yi;
    const float4* Yg4 = (const float4*)g_Yg;

    float4 sv = ((const float4*)so)[d4];
    float4 wv = ((const float4*)gnw)[d4];
    float4 cs = make_float4(wv.x * sv.x, wv.y * sv.y, wv.z * sv.z, wv.w * sv.w);

    float4 h = ((const float4*)g_Cr)[(c * BATCH + b) * (DIM/4) + d4];

    __shared__ float red[2][16];

    for (int t = 0; t < CHLEN; t++) {
        size_t off = base + (size_t)t * (DIM/4);
        float4 f  = Yf4[off];
        float4 yi = Yi4[off];
        h.x = fmaf(f.x, h.x, (1.f - f.x) * yi.x);
        h.y = fmaf(f.y, h.y, (1.f - f.y) * yi.y);
        h.z = fmaf(f.z, h.z, (1.f - f.z) * yi.z);
        h.w = fmaf(f.w, h.w, (1.f - f.w) * yi.w);

        // block reduce sum(h^2): warp shuffle -> parity smem slot -> one barrier
        float ss = h.x*h.x + h.y*h.y + h.z*h.z + h.w*h.w;
        #pragma unroll
        for (int o = 16; o; o >>= 1) ss += __shfl_xor_sync(0xffffffffu, ss, o);
        if (lane == 0) red[t & 1][wid] = ss;
        __syncthreads();
        float tot = 0.f;
        #pragma unroll
        for (int u = 0; u < 16; u++) tot += red[t & 1][u];
        float rms = rsqrtf(tot * (1.f / DIM) + 1e-5f);

        float4 gv = Yg4[off];          // already g*sigmoid(g)
        float q[4];
        q[0] = h.x * rms * cs.x * gv.x;
        q[1] = h.y * rms * cs.y * gv.y;
        q[2] = h.z * rms * cs.z * gv.z;
        q[3] = h.w * rms * cs.w * gv.w;
        __half hi[4]; __half lo[4];
        #pragma unroll
        for (int u = 0; u < 4; u++) {
            hi[u] = __float2half_rn(q[u]);
            lo[u] = __float2half_rn(q[u] - __half2float(hi[u]));
        }
        size_t m = (size_t)(b * SEQ + c * CHLEN + t);
        ((uint2*)(g_A2 + m * (2*DIM)))[d4]       = *(uint2*)hi;
        ((uint2*)(g_A2 + m * (2*DIM) + DIM))[d4] = *(uint2*)lo;
    }
}

// ---------------- launch ----------------
extern "C" void kernel_launch(void* const* d_in, const int* in_sizes, int n_in,
                              void* d_out, int out_size) {
    const float* hs  = (const float*)d_in[0];
    const float* wi  = (const float*)d_in[1];
    const float* wf  = (const float*)d_in[2];
    const float* wg  = (const float*)d_in[3];
    const float* wo  = (const float*)d_in[4];
    const float* si  = (const float*)d_in[5];
    const float* sf  = (const float*)d_in[6];
    const float* sg  = (const float*)d_in[7];
    const float* so  = (const float*)d_in[8];
    const float* gnw = (const float*)d_in[9];

    __half *Xq, *Wi, *Wf, *Wg, *Wo, *A2;
    float  *Yi, *Yf, *Yg;
    cudaGetSymbolAddress((void**)&Xq,  g_Xq);
    cudaGetSymbolAddress((void**)&Wi,  g_Wi);
    cudaGetSymbolAddress((void**)&Wf,  g_Wf);
    cudaGetSymbolAddress((void**)&Wg,  g_Wg);
    cudaGetSymbolAddress((void**)&Wo,  g_Wo);
    cudaGetSymbolAddress((void**)&A2,  g_A2);
    cudaGetSymbolAddress((void**)&Yi,  g_Yi);
    cudaGetSymbolAddress((void**)&Yf,  g_Yf);
    cudaGetSymbolAddress((void**)&Yg,  g_Yg);

    const int smem = NSTAGE * (BM * BK + BN * BK) * 2;  // 96 KB
    cudaFuncSetAttribute(k_gemm, cudaFuncAttributeMaxDynamicSharedMemorySize, smem);
    cudaFuncSetAttribute((const void*)&k_gemm2<2*DIM>,
                         cudaFuncAttributeMaxDynamicSharedMemorySize, smem);

    k_quant<<<(M_TOT * DIM) / 1024, 256>>>(hs);
    k_prepw<<<dim3(DIM / 32, DIM / 32, 4), dim3(32, 8)>>>(wi, wf, wg, wo);

    // i/f/g projections: exact integer fp16 MMA; epilogue applies scale + sigmoid/swish
    k_gemm<<<dim3(DIM / BN, M_TOT / BM, 3), NTHREADS, smem>>>(
        Xq, Wi, Wf, Wg, Yi, Yf, Yg, si, sf, sg, DIM, 0);

    k_scan1<<<dim3(DIM / 512, NCH, BATCH), 128>>>();
    k_scan2<<<(BATCH * DIM / 4) / 256, 256>>>();
    k_scan3norm<<<dim3(NCH, BATCH), 512>>>(so, gnw);

    // output projection: hi/lo K-pairs share one B stage (half the B traffic),
    // BM=64 tiles for wave packing, to_fixed epilogue
    k_gemm2<2*DIM><<<dim3(DIM / BN, M_TOT / 64), NTHREADS, smem>>>(
        A2, Wo, (float*)d_out);
}